// round 1
// baseline (speedup 1.0000x reference)
#include <cuda_runtime.h>
#include <math.h>

// Problem constants
#define B_    2
#define T_    2048
#define HID   1536
#define NH    12
#define DK    16
#define DV    128
#define DF    273          // 1 + 16 + 256 taylor features
#define CH    128          // chunk length
#define NC    (T_/CH)      // 16 chunks
#define BH    (B_*NH)      // 24
#define MROWS (B_*T_)      // 4096

#define INV4R2 0.17677669529663687f   // 1/(4*sqrt(2))

// ---------------- scratch (static device allocations; no cudaMalloc) ----------------
__device__ float g_q [MROWS*NH*DK];      // [b*t][H*dk]
__device__ float g_k [MROWS*NH*DK];
__device__ float g_v [MROWS*NH*DV];      // [b*t][H*dv]
__device__ float g_y [MROWS*NH*DV];
__device__ float g_KV[(size_t)BH*NC*DF*DV];  // per-chunk KV sums -> exclusive states
__device__ float g_K1[(size_t)BH*NC*DF];     // per-chunk kf sums -> exclusive states

// feature f -> (ia, ib, scale) with virtual index 16 == constant 1
__device__ __forceinline__ void fdecomp(int f, int& ia, int& ib, float& sc) {
    if (f == 0)      { ia = 16; ib = 16; sc = 1.f; }
    else if (f < 17) { ia = f - 1; ib = 16; sc = 0.5f; }
    else { int p = f - 17; ia = p >> 4; ib = p & 15; sc = INV4R2; }
}

// ---------------- generic guarded SGEMM: C[M,N] = A[M,K] @ B[N,K]^T ----------------
// K must be a multiple of 16 and rows 16B aligned (true here: K=1536 always).
__global__ __launch_bounds__(256) void sgemm_nt(const float* __restrict__ A,
                                                const float* __restrict__ Bm,
                                                float* __restrict__ C,
                                                int M, int N, int K) {
    __shared__ float As[16][132];
    __shared__ float Bs[16][132];
    const int bm = blockIdx.y * 128;
    const int bn = blockIdx.x * 128;
    const int tid = threadIdx.x;
    const int tx = tid & 15, ty = tid >> 4;
    const int lrow = tid >> 2;          // 0..63
    const int lcol = (tid & 3) << 2;    // 0,4,8,12

    float acc[8][8];
#pragma unroll
    for (int i = 0; i < 8; i++)
#pragma unroll
        for (int j = 0; j < 8; j++) acc[i][j] = 0.f;

    for (int k0 = 0; k0 < K; k0 += 16) {
#pragma unroll
        for (int rr = 0; rr < 2; rr++) {
            int m = bm + lrow + rr*64;
            float4 va = make_float4(0.f,0.f,0.f,0.f);
            if (m < M) va = *(const float4*)&A[(size_t)m*K + k0 + lcol];
            As[lcol+0][lrow+rr*64] = va.x;
            As[lcol+1][lrow+rr*64] = va.y;
            As[lcol+2][lrow+rr*64] = va.z;
            As[lcol+3][lrow+rr*64] = va.w;
            int n = bn + lrow + rr*64;
            float4 vb = make_float4(0.f,0.f,0.f,0.f);
            if (n < N) vb = *(const float4*)&Bm[(size_t)n*K + k0 + lcol];
            Bs[lcol+0][lrow+rr*64] = vb.x;
            Bs[lcol+1][lrow+rr*64] = vb.y;
            Bs[lcol+2][lrow+rr*64] = vb.z;
            Bs[lcol+3][lrow+rr*64] = vb.w;
        }
        __syncthreads();
#pragma unroll
        for (int kk = 0; kk < 16; kk++) {
            float a[8], b[8];
            *(float4*)(a)   = *(const float4*)&As[kk][ty*8];
            *(float4*)(a+4) = *(const float4*)&As[kk][ty*8+4];
            *(float4*)(b)   = *(const float4*)&Bs[kk][tx*8];
            *(float4*)(b+4) = *(const float4*)&Bs[kk][tx*8+4];
#pragma unroll
            for (int i = 0; i < 8; i++)
#pragma unroll
                for (int j = 0; j < 8; j++) acc[i][j] += a[i]*b[j];
        }
        __syncthreads();
    }
#pragma unroll
    for (int i = 0; i < 8; i++) {
        int m = bm + ty*8 + i;
        if (m >= M) continue;
#pragma unroll
        for (int j = 0; j < 8; j += 4) {
            int n = bn + tx*8 + j;
            if (n < N) {
                float4 o = make_float4(acc[i][j], acc[i][j+1], acc[i][j+2], acc[i][j+3]);
                *(float4*)&C[(size_t)m*N + n] = o;
            }
        }
    }
}

// ---------------- Phase A: per-chunk KV[f][e] and K1[f] sums ----------------
// grid: BH*NC blocks; block = (bh, c)
__global__ __launch_bounds__(256) void chunk_kv_kernel() {
    extern __shared__ float sm[];
    float* ks2 = sm;              // [128][17] : k values + ones column
    float* vs  = sm + 128*17;     // [128][128]
    const int bid = blockIdx.x;
    const int bh = bid / NC, c = bid % NC;
    const int b = bh / NH, h = bh % NH;
    const int t0 = c * CH;
    const int tid = threadIdx.x;
    const size_t rowbase = (size_t)(b*T_ + t0);

    for (int idx = tid; idx < 128*16; idx += 256) {
        int t = idx >> 4, i = idx & 15;
        ks2[t*17 + i] = g_k[(rowbase + t)*(NH*DK) + h*DK + i];
    }
    for (int idx = tid; idx < 128; idx += 256) ks2[idx*17 + 16] = 1.f;
    for (int idx = tid; idx < 128*32; idx += 256) {
        int t = idx >> 5, e4 = (idx & 31) << 2;
        *(float4*)&vs[t*128 + e4] =
            *(const float4*)&g_v[(rowbase + t)*(NH*DV) + h*DV + e4];
    }
    __syncthreads();

    for (int task = tid; task < DF*16; task += 256) {
        int f = task >> 4, e0 = (task & 15) << 3;
        int ia, ib; float sc; fdecomp(f, ia, ib, sc);
        float a0=0,a1=0,a2=0,a3=0,a4=0,a5=0,a6=0,a7=0;
#pragma unroll 4
        for (int t = 0; t < 128; t++) {
            float kf = ks2[t*17+ia] * ks2[t*17+ib];
            float4 v0 = *(float4*)&vs[t*128 + e0];
            float4 v1 = *(float4*)&vs[t*128 + e0 + 4];
            a0 += kf*v0.x; a1 += kf*v0.y; a2 += kf*v0.z; a3 += kf*v0.w;
            a4 += kf*v1.x; a5 += kf*v1.y; a6 += kf*v1.z; a7 += kf*v1.w;
        }
        size_t base = ((size_t)bid*DF + f)*DV + e0;
        *(float4*)&g_KV[base]   = make_float4(a0*sc, a1*sc, a2*sc, a3*sc);
        *(float4*)&g_KV[base+4] = make_float4(a4*sc, a5*sc, a6*sc, a7*sc);
    }
    for (int f = tid; f < DF; f += 256) {
        int ia, ib; float sc; fdecomp(f, ia, ib, sc);
        float s = 0.f;
#pragma unroll 4
        for (int t = 0; t < 128; t++) s += ks2[t*17+ia]*ks2[t*17+ib];
        g_K1[(size_t)bid*DF + f] = s*sc;
    }
}

// ---------------- Phase B: exclusive prefix scan over chunks ----------------
__global__ __launch_bounds__(256) void scan_kernel() {
    const int bh = blockIdx.x;
    const int part = blockIdx.y;             // 0..17
    const int stride = 18*256;
    size_t baseKV = (size_t)bh*NC*DF*DV;
    for (int idx = part*256 + threadIdx.x; idx < DF*DV; idx += stride) {
        float prev = 0.f;
        size_t p = baseKV + idx;
#pragma unroll
        for (int cc = 0; cc < NC; cc++) {
            float tmp = g_KV[p]; g_KV[p] = prev; prev += tmp;
            p += (size_t)DF*DV;
        }
    }
    if (part == 0) {
        size_t baseK = (size_t)bh*NC*DF;
        for (int idx = threadIdx.x; idx < DF; idx += 256) {
            float prev = 0.f; size_t p = baseK + idx;
#pragma unroll
            for (int cc = 0; cc < NC; cc++) {
                float tmp = g_K1[p]; g_K1[p] = prev; prev += tmp; p += DF;
            }
        }
    }
}

// ---------------- Phase C: fused inter + intra chunk attention ----------------
// grid: BH*NC blocks; block = (bh, c); 256 threads, 8x8 register tiles over (t,e)
__global__ __launch_bounds__(256) void attn_kernel() {
    extern __shared__ float sm[];
    float* qT2 = sm;                 // [17][128] q values (+ones row 16), f-major
    float* kT  = qT2 + 17*128;       // [16][128]
    float* Ss  = kT  + 16*128;       // [128][132] masked phi scores
    float* tA  = Ss  + 128*132;      // [16][128] qf tile (f-chunk)
    float* tB  = tA  + 16*128;       // [16][128] state / v tile
    float* stK = tB  + 16*128;       // [288] exclusive K1 state
    float* dsh = stK + 288;          // [128] denominators

    const int bid = blockIdx.x;
    const int bh = bid / NC, c = bid % NC;
    const int b = bh / NH, h = bh % NH;
    const int t0 = c * CH;
    const int tid = threadIdx.x;
    const int tx = tid & 15, ty = tid >> 4;
    const size_t rowbase = (size_t)(b*T_ + t0);

    for (int idx = tid; idx < 128*16; idx += 256) {
        int t = idx >> 4, i = idx & 15;
        qT2[i*128 + t] = g_q[(rowbase + t)*(NH*DK) + h*DK + i];
        kT [i*128 + t] = g_k[(rowbase + t)*(NH*DK) + h*DK + i];
    }
    for (int idx = tid; idx < 128; idx += 256) qT2[16*128 + idx] = 1.f;
    for (int f = tid; f < DF; f += 256) stK[f] = g_K1[(size_t)bid*DF + f];
    __syncthreads();

    // ---- S[t][s] = phi(q_t . k_s), causal mask; phi(x)=1+x/4+x^2/32 ----
    {
        float sacc[8][8];
#pragma unroll
        for (int i = 0; i < 8; i++)
#pragma unroll
            for (int j = 0; j < 8; j++) sacc[i][j] = 0.f;
#pragma unroll
        for (int kk = 0; kk < 16; kk++) {
            float a[8], bb[8];
            *(float4*)(a)    = *(const float4*)&qT2[kk*128 + ty*8];
            *(float4*)(a+4)  = *(const float4*)&qT2[kk*128 + ty*8 + 4];
            *(float4*)(bb)   = *(const float4*)&kT [kk*128 + tx*8];
            *(float4*)(bb+4) = *(const float4*)&kT [kk*128 + tx*8 + 4];
#pragma unroll
            for (int i = 0; i < 8; i++)
#pragma unroll
                for (int j = 0; j < 8; j++) sacc[i][j] += a[i]*bb[j];
        }
#pragma unroll
        for (int i = 0; i < 8; i++) {
            int t = ty*8 + i;
#pragma unroll
            for (int j = 0; j < 8; j++) {
                int s = tx*8 + j;
                float d = sacc[i][j];
                Ss[t*132 + s] = (s <= t) ? (1.f + 0.25f*d + 0.03125f*d*d) : 0.f;
            }
        }
    }
    __syncthreads();

    // ---- denominators: qf . stateK  +  rowsum(S) + EPS ----
    if (tid < 128) {
        const int t = tid;
        float qv[16];
#pragma unroll
        for (int i = 0; i < 16; i++) qv[i] = qT2[i*128 + t];
        float dacc = stK[0];
#pragma unroll
        for (int i = 0; i < 16; i++) dacc += qv[i]*0.5f*stK[1+i];
#pragma unroll
        for (int i = 0; i < 16; i++) {
            float qi = qv[i]*INV4R2;
#pragma unroll
            for (int j = 0; j < 16; j++)
                dacc += qi*qv[j]*stK[17 + i*16 + j];
        }
        float di = 0.f;
        for (int s = 0; s < 128; s++) di += Ss[t*132 + s];
        dsh[t] = dacc + di + 1e-12f;
    }
    __syncthreads();

    float acc[8][8];
#pragma unroll
    for (int i = 0; i < 8; i++)
#pragma unroll
        for (int j = 0; j < 8; j++) acc[i][j] = 0.f;

    // ---- inter-chunk: y += qf @ stateKV  (18 f-chunks of 16, padded) ----
    for (int fc = 0; fc < 18; fc++) {
        const int f0 = fc * 16;
        for (int idx = tid; idx < 2048; idx += 256) {
            int kk = idx >> 7, t = idx & 127;
            int f = f0 + kk;
            float val = 0.f;
            if (f < DF) {
                int ia, ib; float scl; fdecomp(f, ia, ib, scl);
                val = qT2[ia*128 + t] * qT2[ib*128 + t] * scl;
            }
            tA[kk*128 + t] = val;
        }
        for (int idx = tid; idx < 512; idx += 256) {
            int kk = idx >> 5, e4 = (idx & 31) << 2;
            int f = f0 + kk;
            float4 v = make_float4(0.f,0.f,0.f,0.f);
            if (f < DF) v = *(const float4*)&g_KV[((size_t)bid*DF + f)*DV + e4];
            *(float4*)&tB[kk*128 + e4] = v;
        }
        __syncthreads();
#pragma unroll
        for (int kk = 0; kk < 16; kk++) {
            float a[8], bb[8];
            *(float4*)(a)    = *(const float4*)&tA[kk*128 + ty*8];
            *(float4*)(a+4)  = *(const float4*)&tA[kk*128 + ty*8 + 4];
            *(float4*)(bb)   = *(const float4*)&tB[kk*128 + tx*8];
            *(float4*)(bb+4) = *(const float4*)&tB[kk*128 + tx*8 + 4];
#pragma unroll
            for (int i = 0; i < 8; i++)
#pragma unroll
                for (int j = 0; j < 8; j++) acc[i][j] += a[i]*bb[j];
        }
        __syncthreads();
    }

    // ---- intra-chunk: y += S @ v  (8 s-chunks of 16) ----
    for (int scn = 0; scn < 8; scn++) {
        const int s0 = scn * 16;
        for (int idx = tid; idx < 512; idx += 256) {
            int kk = idx >> 5, e4 = (idx & 31) << 2;
            *(float4*)&tB[kk*128 + e4] =
                *(const float4*)&g_v[(rowbase + s0 + kk)*(NH*DV) + h*DV + e4];
        }
        __syncthreads();
#pragma unroll
        for (int kk = 0; kk < 16; kk++) {
            float bb[8];
            *(float4*)(bb)   = *(const float4*)&tB[kk*128 + tx*8];
            *(float4*)(bb+4) = *(const float4*)&tB[kk*128 + tx*8 + 4];
#pragma unroll
            for (int i = 0; i < 8; i++) {
                float a = Ss[(ty*8+i)*132 + s0 + kk];
#pragma unroll
                for (int j = 0; j < 8; j++) acc[i][j] += a*bb[j];
            }
        }
        __syncthreads();
    }

    // ---- epilogue: divide by den, write y ----
#pragma unroll
    for (int i = 0; i < 8; i++) {
        int t = ty*8 + i;
        float r = 1.f / dsh[t];
        size_t row = (rowbase + t)*(NH*DV) + h*DV + tx*8;
        *(float4*)&g_y[row]   = make_float4(acc[i][0]*r, acc[i][1]*r, acc[i][2]*r, acc[i][3]*r);
        *(float4*)&g_y[row+4] = make_float4(acc[i][4]*r, acc[i][5]*r, acc[i][6]*r, acc[i][7]*r);
    }
}

// ---------------- launch ----------------
extern "C" void kernel_launch(void* const* d_in, const int* in_sizes, int n_in,
                              void* d_out, int out_size) {
    const float* hs = (const float*)d_in[0];
    const float* Wq = (const float*)d_in[1];
    const float* Wk = (const float*)d_in[2];
    const float* Wv = (const float*)d_in[3];
    const float* Wo = (const float*)d_in[4];
    float* out = (float*)d_out;

    float *q, *k, *v, *y;
    cudaGetSymbolAddress((void**)&q, g_q);
    cudaGetSymbolAddress((void**)&k, g_k);
    cudaGetSymbolAddress((void**)&v, g_v);
    cudaGetSymbolAddress((void**)&y, g_y);

    const int SMEM_A = (128*17 + 128*128) * 4;                    // 74240 B
    const int SMEM_C = (17*128 + 16*128 + 128*132 + 16*128 + 16*128 + 288 + 128) * 4; // 102528 B
    cudaFuncSetAttribute(chunk_kv_kernel, cudaFuncAttributeMaxDynamicSharedMemorySize, SMEM_A);
    cudaFuncSetAttribute(attn_kernel,     cudaFuncAttributeMaxDynamicSharedMemorySize, SMEM_C);

    dim3 thr(256);
    // projections: q, k: [4096,1536]@[192,1536]^T ; v: @[1536,1536]^T
    sgemm_nt<<<dim3(2, 32),  thr>>>(hs, Wq, q, MROWS, NH*DK, HID);
    sgemm_nt<<<dim3(2, 32),  thr>>>(hs, Wk, k, MROWS, NH*DK, HID);
    sgemm_nt<<<dim3(12, 32), thr>>>(hs, Wv, v, MROWS, NH*DV, HID);

    chunk_kv_kernel<<<BH*NC, thr, SMEM_A>>>();
    scan_kernel<<<dim3(BH, 18), thr>>>();
    attn_kernel<<<BH*NC, thr, SMEM_C>>>();

    // out = y @ Wo^T
    sgemm_nt<<<dim3(12, 32), thr>>>(y, Wo, out, MROWS, HID, NH*DV);
}

// round 4
// speedup vs baseline: 1.3853x; 1.3853x over previous
#include <cuda_runtime.h>
#include <math.h>

// Problem constants
#define B_    2
#define T_    2048
#define HID   1536
#define NH    12
#define DK    16
#define DV    128
#define DF    273          // 1 + 16 + 256 taylor features
#define CH    128          // chunk length
#define NC    (T_/CH)      // 16 chunks
#define BH    (B_*NH)      // 24
#define MROWS (B_*T_)      // 4096

#define INV4R2 0.17677669529663687f   // 1/(4*sqrt(2))

// ---------------- scratch (static device allocations; no cudaMalloc) ----------------
__device__ float g_q [MROWS*NH*DK];      // [b*t][H*dk]
__device__ float g_k [MROWS*NH*DK];
__device__ float g_v [MROWS*NH*DV];      // [b*t][H*dv]
__device__ float g_y [MROWS*NH*DV];
__device__ float g_KV[(size_t)BH*NC*DF*DV];  // per-chunk KV sums -> exclusive states
__device__ float g_K1[(size_t)BH*NC*DF];     // per-chunk kf sums -> exclusive states

// feature f -> (ia, ib, scale) with virtual index 16 == constant 1
__device__ __forceinline__ void fdecomp(int f, int& ia, int& ib, float& sc) {
    if (f == 0)      { ia = 16; ib = 16; sc = 1.f; }
    else if (f < 17) { ia = f - 1; ib = 16; sc = 0.5f; }
    else { int p = f - 17; ia = p >> 4; ib = p & 15; sc = INV4R2; }
}

// ---------------- double-buffered SGEMM: C[M,N] = A[M,K] @ B[N,K]^T ----------------
// K multiple of 16, rows 16B aligned (K=1536 here).
__device__ __forceinline__ void ld_panel(const float* __restrict__ A,
                                         const float* __restrict__ Bm,
                                         int M, int N, int K, int bm, int bn, int k0,
                                         int lrow, int lcol, float4* va, float4* vb) {
#pragma unroll
    for (int rr = 0; rr < 2; rr++) {
        int m = bm + lrow + rr*64;
        va[rr] = make_float4(0.f,0.f,0.f,0.f);
        if (m < M) va[rr] = *(const float4*)&A[(size_t)m*K + k0 + lcol];
        int n = bn + lrow + rr*64;
        vb[rr] = make_float4(0.f,0.f,0.f,0.f);
        if (n < N) vb[rr] = *(const float4*)&Bm[(size_t)n*K + k0 + lcol];
    }
}
__device__ __forceinline__ void st_panel(float (*As)[132], float (*Bs)[132],
                                         int lrow, int lcol, const float4* va, const float4* vb) {
#pragma unroll
    for (int rr = 0; rr < 2; rr++) {
        As[lcol+0][lrow+rr*64] = va[rr].x;
        As[lcol+1][lrow+rr*64] = va[rr].y;
        As[lcol+2][lrow+rr*64] = va[rr].z;
        As[lcol+3][lrow+rr*64] = va[rr].w;
        Bs[lcol+0][lrow+rr*64] = vb[rr].x;
        Bs[lcol+1][lrow+rr*64] = vb[rr].y;
        Bs[lcol+2][lrow+rr*64] = vb[rr].z;
        Bs[lcol+3][lrow+rr*64] = vb[rr].w;
    }
}

__device__ __forceinline__ void sgemm_body(const float* __restrict__ A,
                                           const float* __restrict__ Bm,
                                           float* __restrict__ C,
                                           int M, int N, int K, int bm, int bn) {
    __shared__ float As[2][16][132];
    __shared__ float Bs[2][16][132];
    const int tid = threadIdx.x;
    const int tx = tid & 15, ty = tid >> 4;
    const int lrow = tid >> 2;
    const int lcol = (tid & 3) << 2;

    float acc[8][8];
#pragma unroll
    for (int i = 0; i < 8; i++)
#pragma unroll
        for (int j = 0; j < 8; j++) acc[i][j] = 0.f;

    const int nk = K >> 4;
    float4 va[2], vb[2];
    ld_panel(A, Bm, M, N, K, bm, bn, 0, lrow, lcol, va, vb);
    st_panel(As[0], Bs[0], lrow, lcol, va, vb);
    __syncthreads();

    for (int kp = 0; kp < nk; kp++) {
        const int cur = kp & 1;
        if (kp + 1 < nk)
            ld_panel(A, Bm, M, N, K, bm, bn, (kp+1) << 4, lrow, lcol, va, vb);
#pragma unroll
        for (int kk = 0; kk < 16; kk++) {
            float a[8], b[8];
            *(float4*)(a)   = *(const float4*)&As[cur][kk][ty*8];
            *(float4*)(a+4) = *(const float4*)&As[cur][kk][ty*8+4];
            *(float4*)(b)   = *(const float4*)&Bs[cur][kk][tx*8];
            *(float4*)(b+4) = *(const float4*)&Bs[cur][kk][tx*8+4];
#pragma unroll
            for (int i = 0; i < 8; i++)
#pragma unroll
                for (int j = 0; j < 8; j++) acc[i][j] += a[i]*b[j];
        }
        if (kp + 1 < nk)
            st_panel(As[cur^1], Bs[cur^1], lrow, lcol, va, vb);
        __syncthreads();
    }
#pragma unroll
    for (int i = 0; i < 8; i++) {
        int m = bm + ty*8 + i;
        if (m >= M) continue;
#pragma unroll
        for (int j = 0; j < 8; j += 4) {
            int n = bn + tx*8 + j;
            if (n < N) {
                float4 o = make_float4(acc[i][j], acc[i][j+1], acc[i][j+2], acc[i][j+3]);
                *(float4*)&C[(size_t)m*N + n] = o;
            }
        }
    }
}

__global__ __launch_bounds__(256) void sgemm_nt(const float* __restrict__ A,
                                                const float* __restrict__ Bm,
                                                float* __restrict__ C,
                                                int M, int N, int K) {
    sgemm_body(A, Bm, C, M, N, K, blockIdx.y * 128, blockIdx.x * 128);
}

// fused q+k projection: z=0 -> Wq->g_q, z=1 -> Wk->g_k
__global__ __launch_bounds__(256) void sgemm_qk(const float* __restrict__ A,
                                                const float* __restrict__ Wq,
                                                const float* __restrict__ Wk) {
    const float* Bm = (blockIdx.z == 0) ? Wq : Wk;
    float* C = (blockIdx.z == 0) ? g_q : g_k;
    sgemm_body(A, Bm, C, MROWS, NH*DK, HID, blockIdx.y * 128, blockIdx.x * 128);
}

// ---------------- Phase A: per-chunk KV[f][e] and K1[f] sums (register-tiled GEMM) ----------------
// grid: BH*NC blocks; block = (bh, c)
__global__ __launch_bounds__(256) void chunk_kv_kernel() {
    extern __shared__ float sm[];
    float* ks2 = sm;              // [128][17] : k values + ones column
    float* vs  = sm + 128*17;     // [128][132] (padded)
    float* tA  = vs + 128*132;    // [16][128] : kf panel, layout [tt][f_local]
    const int bid = blockIdx.x;
    const int bh = bid / NC, c = bid % NC;
    const int b = bh / NH, h = bh % NH;
    const int t0c = c * CH;
    const int tid = threadIdx.x;
    const int tx = tid & 15, ty = tid >> 4;
    const size_t rowbase = (size_t)(b*T_ + t0c);

    for (int idx = tid; idx < 128*16; idx += 256) {
        int t = idx >> 4, i = idx & 15;
        ks2[t*17 + i] = g_k[(rowbase + t)*(NH*DK) + h*DK + i];
    }
    for (int idx = tid; idx < 128; idx += 256) ks2[idx*17 + 16] = 1.f;
    for (int idx = tid; idx < 128*32; idx += 256) {
        int t = idx >> 5, e4 = (idx & 31) << 2;
        *(float4*)&vs[t*132 + e4] =
            *(const float4*)&g_v[(rowbase + t)*(NH*DV) + h*DV + e4];
    }
    __syncthreads();

    // KV[f][e] = sum_t kf[f][t] * v[t][e]; 3 f-subtiles of 128 (last padded)
    for (int fsub = 0; fsub < 3; fsub++) {
        const int fbase = fsub * 128;
        float acc[8][8];
#pragma unroll
        for (int i = 0; i < 8; i++)
#pragma unroll
            for (int j = 0; j < 8; j++) acc[i][j] = 0.f;

        for (int tp = 0; tp < 8; tp++) {
            const int t0 = tp * 16;
            for (int idx = tid; idx < 2048; idx += 256) {
                int tt = idx >> 7, fl = idx & 127;
                int f = fbase + fl;
                float val = 0.f;
                if (f < DF) {
                    int ia, ib; float sc; fdecomp(f, ia, ib, sc);
                    val = ks2[(t0+tt)*17 + ia] * ks2[(t0+tt)*17 + ib] * sc;
                }
                tA[tt*128 + fl] = val;
            }
            __syncthreads();
#pragma unroll
            for (int tt = 0; tt < 16; tt++) {
                float a[8], bb[8];
                *(float4*)(a)    = *(const float4*)&tA[tt*128 + ty*8];
                *(float4*)(a+4)  = *(const float4*)&tA[tt*128 + ty*8 + 4];
                *(float4*)(bb)   = *(const float4*)&vs[(t0+tt)*132 + tx*8];
                *(float4*)(bb+4) = *(const float4*)&vs[(t0+tt)*132 + tx*8 + 4];
#pragma unroll
                for (int i = 0; i < 8; i++)
#pragma unroll
                    for (int j = 0; j < 8; j++) acc[i][j] += a[i]*bb[j];
            }
            __syncthreads();
        }
#pragma unroll
        for (int i = 0; i < 8; i++) {
            int f = fbase + ty*8 + i;
            if (f >= DF) continue;
            size_t base = ((size_t)bid*DF + f)*DV + tx*8;
            *(float4*)&g_KV[base]   = make_float4(acc[i][0], acc[i][1], acc[i][2], acc[i][3]);
            *(float4*)&g_KV[base+4] = make_float4(acc[i][4], acc[i][5], acc[i][6], acc[i][7]);
        }
    }

    // K1[f] = sum_t kf[f][t]
    for (int f = tid; f < DF; f += 256) {
        int ia, ib; float sc; fdecomp(f, ia, ib, sc);
        float s = 0.f;
#pragma unroll 4
        for (int t = 0; t < 128; t++) s += ks2[t*17+ia]*ks2[t*17+ib];
        g_K1[(size_t)bid*DF + f] = s*sc;
    }
}

// ---------------- Phase B: exclusive prefix scan over chunks ----------------
__global__ __launch_bounds__(256) void scan_kernel() {
    const int bh = blockIdx.x;
    const int part = blockIdx.y;             // 0..17
    const int stride = 18*256;
    size_t baseKV = (size_t)bh*NC*DF*DV;
    for (int idx = part*256 + threadIdx.x; idx < DF*DV; idx += stride) {
        float prev = 0.f;
        size_t p = baseKV + idx;
#pragma unroll
        for (int cc = 0; cc < NC; cc++) {
            float tmp = g_KV[p]; g_KV[p] = prev; prev += tmp;
            p += (size_t)DF*DV;
        }
    }
    if (part == 0) {
        size_t baseK = (size_t)bh*NC*DF;
        for (int idx = threadIdx.x; idx < DF; idx += 256) {
            float prev = 0.f; size_t p = baseK + idx;
#pragma unroll
            for (int cc = 0; cc < NC; cc++) {
                float tmp = g_K1[p]; g_K1[p] = prev; prev += tmp; p += DF;
            }
        }
    }
}

// ---------------- Phase C: fused inter + intra chunk attention ----------------
__global__ __launch_bounds__(256) void attn_kernel() {
    extern __shared__ float sm[];
    float* qT2 = sm;                 // [17][128] q values (+ones row 16), f-major
    float* kT  = qT2 + 17*128;       // [16][128]
    float* Ss  = kT  + 16*128;       // [128][132] masked phi scores
    float* tA  = Ss  + 128*132;      // [16][128] qf tile (f-chunk)
    float* tB  = tA  + 16*128;       // [16][128] state / v tile
    float* stK = tB  + 16*128;       // [288] exclusive K1 state
    float* dsh = stK + 288;          // [128] denominators

    const int bid = blockIdx.x;
    const int bh = bid / NC, c = bid % NC;
    const int b = bh / NH, h = bh % NH;
    const int t0 = c * CH;
    const int tid = threadIdx.x;
    const int tx = tid & 15, ty = tid >> 4;
    const size_t rowbase = (size_t)(b*T_ + t0);

    for (int idx = tid; idx < 128*16; idx += 256) {
        int t = idx >> 4, i = idx & 15;
        qT2[i*128 + t] = g_q[(rowbase + t)*(NH*DK) + h*DK + i];
        kT [i*128 + t] = g_k[(rowbase + t)*(NH*DK) + h*DK + i];
    }
    for (int idx = tid; idx < 128; idx += 256) qT2[16*128 + idx] = 1.f;
    for (int f = tid; f < DF; f += 256) stK[f] = g_K1[(size_t)bid*DF + f];
    __syncthreads();

    // ---- S[t][s] = phi(q_t . k_s), causal mask; phi(x)=1+x/4+x^2/32 ----
    {
        float sacc[8][8];
#pragma unroll
        for (int i = 0; i < 8; i++)
#pragma unroll
            for (int j = 0; j < 8; j++) sacc[i][j] = 0.f;
#pragma unroll
        for (int kk = 0; kk < 16; kk++) {
            float a[8], bb[8];
            *(float4*)(a)    = *(const float4*)&qT2[kk*128 + ty*8];
            *(float4*)(a+4)  = *(const float4*)&qT2[kk*128 + ty*8 + 4];
            *(float4*)(bb)   = *(const float4*)&kT [kk*128 + tx*8];
            *(float4*)(bb+4) = *(const float4*)&kT [kk*128 + tx*8 + 4];
#pragma unroll
            for (int i = 0; i < 8; i++)
#pragma unroll
                for (int j = 0; j < 8; j++) sacc[i][j] += a[i]*bb[j];
        }
#pragma unroll
        for (int i = 0; i < 8; i++) {
            int t = ty*8 + i;
#pragma unroll
            for (int j = 0; j < 8; j++) {
                int s = tx*8 + j;
                float d = sacc[i][j];
                Ss[t*132 + s] = (s <= t) ? (1.f + 0.25f*d + 0.03125f*d*d) : 0.f;
            }
        }
    }
    __syncthreads();

    // ---- denominators: qf . stateK  +  rowsum(S) + EPS ----
    if (tid < 128) {
        const int t = tid;
        float qv[16];
#pragma unroll
        for (int i = 0; i < 16; i++) qv[i] = qT2[i*128 + t];
        float dacc = stK[0];
#pragma unroll
        for (int i = 0; i < 16; i++) dacc += qv[i]*0.5f*stK[1+i];
#pragma unroll
        for (int i = 0; i < 16; i++) {
            float qi = qv[i]*INV4R2;
#pragma unroll
            for (int j = 0; j < 16; j++)
                dacc += qi*qv[j]*stK[17 + i*16 + j];
        }
        float di = 0.f;
        for (int s = 0; s < 128; s++) di += Ss[t*132 + s];
        dsh[t] = dacc + di + 1e-12f;
    }
    __syncthreads();

    float acc[8][8];
#pragma unroll
    for (int i = 0; i < 8; i++)
#pragma unroll
        for (int j = 0; j < 8; j++) acc[i][j] = 0.f;

    // ---- inter-chunk: y += qf @ stateKV  (18 f-chunks of 16, padded) ----
    for (int fc = 0; fc < 18; fc++) {
        const int f0 = fc * 16;
        for (int idx = tid; idx < 2048; idx += 256) {
            int kk = idx >> 7, t = idx & 127;
            int f = f0 + kk;
            float val = 0.f;
            if (f < DF) {
                int ia, ib; float scl; fdecomp(f, ia, ib, scl);
                val = qT2[ia*128 + t] * qT2[ib*128 + t] * scl;
            }
            tA[kk*128 + t] = val;
        }
        for (int idx = tid; idx < 512; idx += 256) {
            int kk = idx >> 5, e4 = (idx & 31) << 2;
            int f = f0 + kk;
            float4 v = make_float4(0.f,0.f,0.f,0.f);
            if (f < DF) v = *(const float4*)&g_KV[((size_t)bid*DF + f)*DV + e4];
            *(float4*)&tB[kk*128 + e4] = v;
        }
        __syncthreads();
#pragma unroll
        for (int kk = 0; kk < 16; kk++) {
            float a[8], bb[8];
            *(float4*)(a)    = *(const float4*)&tA[kk*128 + ty*8];
            *(float4*)(a+4)  = *(const float4*)&tA[kk*128 + ty*8 + 4];
            *(float4*)(bb)   = *(const float4*)&tB[kk*128 + tx*8];
            *(float4*)(bb+4) = *(const float4*)&tB[kk*128 + tx*8 + 4];
#pragma unroll
            for (int i = 0; i < 8; i++)
#pragma unroll
                for (int j = 0; j < 8; j++) acc[i][j] += a[i]*bb[j];
        }
        __syncthreads();
    }

    // ---- intra-chunk: y += S @ v  (8 s-chunks of 16) ----
    for (int scn = 0; scn < 8; scn++) {
        const int s0 = scn * 16;
        for (int idx = tid; idx < 512; idx += 256) {
            int kk = idx >> 5, e4 = (idx & 31) << 2;
            *(float4*)&tB[kk*128 + e4] =
                *(const float4*)&g_v[(rowbase + s0 + kk)*(NH*DV) + h*DV + e4];
        }
        __syncthreads();
#pragma unroll
        for (int kk = 0; kk < 16; kk++) {
            float bb[8];
            *(float4*)(bb)   = *(const float4*)&tB[kk*128 + tx*8];
            *(float4*)(bb+4) = *(const float4*)&tB[kk*128 + tx*8 + 4];
#pragma unroll
            for (int i = 0; i < 8; i++) {
                float a = Ss[(ty*8+i)*132 + s0 + kk];
#pragma unroll
                for (int j = 0; j < 8; j++) acc[i][j] += a*bb[j];
            }
        }
        __syncthreads();
    }

    // ---- epilogue: divide by den, write y ----
#pragma unroll
    for (int i = 0; i < 8; i++) {
        int t = ty*8 + i;
        float r = 1.f / dsh[t];
        size_t row = (rowbase + t)*(NH*DV) + h*DV + tx*8;
        *(float4*)&g_y[row]   = make_float4(acc[i][0]*r, acc[i][1]*r, acc[i][2]*r, acc[i][3]*r);
        *(float4*)&g_y[row+4] = make_float4(acc[i][4]*r, acc[i][5]*r, acc[i][6]*r, acc[i][7]*r);
    }
}

// ---------------- launch ----------------
extern "C" void kernel_launch(void* const* d_in, const int* in_sizes, int n_in,
                              void* d_out, int out_size) {
    const float* hs = (const float*)d_in[0];
    const float* Wq = (const float*)d_in[1];
    const float* Wk = (const float*)d_in[2];
    const float* Wv = (const float*)d_in[3];
    const float* Wo = (const float*)d_in[4];
    float* out = (float*)d_out;

    float *v, *y;
    cudaGetSymbolAddress((void**)&v, g_v);
    cudaGetSymbolAddress((void**)&y, g_y);

    const int SMEM_A = (128*17 + 128*132 + 16*128) * 4;           // 84480 B
    const int SMEM_C = (17*128 + 16*128 + 128*132 + 16*128 + 16*128 + 288 + 128) * 4; // 102528 B
    cudaFuncSetAttribute(chunk_kv_kernel, cudaFuncAttributeMaxDynamicSharedMemorySize, SMEM_A);
    cudaFuncSetAttribute(attn_kernel,     cudaFuncAttributeMaxDynamicSharedMemorySize, SMEM_C);

    dim3 thr(256);
    // fused q,k projections: [4096,1536]@[192,1536]^T  (z selects Wq/Wk)
    sgemm_qk<<<dim3(2, 32, 2), thr>>>(hs, Wq, Wk);
    // v projection: @[1536,1536]^T
    sgemm_nt<<<dim3(12, 32), thr>>>(hs, Wv, v, MROWS, NH*DV, HID);

    chunk_kv_kernel<<<BH*NC, thr, SMEM_A>>>();
    scan_kernel<<<dim3(BH, 18), thr>>>();
    attn_kernel<<<BH*NC, thr, SMEM_C>>>();

    // out = y @ Wo^T
    sgemm_nt<<<dim3(12, 32), thr>>>(y, Wo, out, MROWS, HID, NH*DV);
}

// round 8
// speedup vs baseline: 2.2006x; 1.5886x over previous
#include <cuda_runtime.h>
#include <cuda_bf16.h>
#include <cstdint>
#include <math.h>

// Problem constants
#define B_    2
#define T_    2048
#define HID   1536
#define NH    12
#define DK    16
#define DV    128
#define DF    273          // 1 + 16 + 256 taylor features
#define CH    128          // chunk length
#define NC    (T_/CH)      // 16 chunks
#define BH    (B_*NH)      // 24
#define MROWS (B_*T_)      // 4096
#define NQK   384          // q|k combined output cols (192+192)
#define GK    1536         // GEMM K (always hid or H*dv=1536; qk N=384)

#define INV4R2 0.17677669529663687f   // 1/(4*sqrt(2))

// ---------------- scratch (static device allocations; no cudaMalloc) ----------------
__device__ float g_qk[MROWS*NQK];        // [b*t][ q(0..191) | k(192..383) ]
__device__ float g_v [MROWS*NH*DV];      // [b*t][H*dv]
__device__ float g_y [MROWS*NH*DV];
__device__ float g_KV[(size_t)BH*NC*DF*DV];
__device__ float g_K1[(size_t)BH*NC*DF];

// bf16 split buffers
__device__ __nv_bfloat16 g_hsH[MROWS*HID], g_hsL[MROWS*HID];
__device__ __nv_bfloat16 g_wqkH[NQK*HID],  g_wqkL[NQK*HID];
__device__ __nv_bfloat16 g_wvH[HID*HID],   g_wvL[HID*HID];
__device__ __nv_bfloat16 g_woH[HID*HID],   g_woL[HID*HID];
__device__ __nv_bfloat16 g_yH[MROWS*HID],  g_yL[MROWS*HID];

// ---------------- portable PTX helpers (valid on compute_103 base target) ----------------
__device__ __forceinline__ uint32_t smem_to_u32(const void* p) {
    uint32_t a;
    asm("{ .reg .u64 t; cvta.to.shared.u64 t, %1; cvt.u32.u64 %0, t; }" : "=r"(a) : "l"(p));
    return a;
}
#define CP_ASYNC16(dst, src) \
    asm volatile("cp.async.cg.shared.global [%0], [%1], 16;" :: "r"(dst), "l"(src) : "memory")
#define CP_COMMIT() asm volatile("cp.async.commit_group;" ::: "memory")
#define CP_WAIT1()  asm volatile("cp.async.wait_group 1;" ::: "memory")
#define CP_WAIT0()  asm volatile("cp.async.wait_group 0;" ::: "memory")

#define LDSM4(r0, r1, r2, r3, addr) \
    asm volatile("ldmatrix.sync.aligned.m8n8.x4.shared.b16 {%0,%1,%2,%3}, [%4];" \
        : "=r"(r0), "=r"(r1), "=r"(r2), "=r"(r3) : "r"(addr))
#define LDSM2(r0, r1, addr) \
    asm volatile("ldmatrix.sync.aligned.m8n8.x2.shared.b16 {%0,%1}, [%2];" \
        : "=r"(r0), "=r"(r1) : "r"(addr))

#define MMA16816(c, a, b) \
    asm volatile("mma.sync.aligned.m16n8k16.row.col.f32.bf16.bf16.f32 " \
        "{%0,%1,%2,%3}, {%4,%5,%6,%7}, {%8,%9}, {%0,%1,%2,%3};" \
        : "+f"((c)[0]), "+f"((c)[1]), "+f"((c)[2]), "+f"((c)[3]) \
        : "r"((a)[0]), "r"((a)[1]), "r"((a)[2]), "r"((a)[3]), "r"((b)[0]), "r"((b)[1]))

// feature f -> (ia, ib, scale) with virtual index 16 == constant 1
__device__ __forceinline__ void fdecomp(int f, int& ia, int& ib, float& sc) {
    if (f == 0)      { ia = 16; ib = 16; sc = 1.f; }
    else if (f < 17) { ia = f - 1; ib = 16; sc = 0.5f; }
    else { int p = f - 17; ia = p >> 4; ib = p & 15; sc = INV4R2; }
}

// ---------------- split-convert: fp32 -> (bf16 hi, bf16 lo) ----------------
__global__ __launch_bounds__(256) void conv_split(const float* __restrict__ src,
                                                  __nv_bfloat16* __restrict__ hi,
                                                  __nv_bfloat16* __restrict__ lo, int n) {
    for (int i = blockIdx.x*256 + threadIdx.x; i < n; i += gridDim.x*256) {
        float x = src[i];
        __nv_bfloat16 h = __float2bfloat16(x);
        hi[i] = h;
        lo[i] = __float2bfloat16(x - __bfloat162float(h));
    }
}

// ---------------- HMMA split-bf16 GEMM: C[M,N] = A[M,K]@B[N,K]^T ----------------
// C = Ah*Bh + Ah*Bl + Al*Bh (fp32 accumulate). M=grid.y*128, N=grid.x*128, K=1536.
// smem: 2 stages x 4 tiles (Ah,Al,Bh,Bl), each 128 rows x 32 bf16, stride 40.
#define TSTRIDE 40
#define TILE_SB (128*TSTRIDE*2)        // 10240 B per tile
#define STAGE_SB (4*TILE_SB)           // 40960 B per stage
#define SMEM_G  (2*STAGE_SB)           // 81920 B
#define NSTAGE  (GK/32)                // 48

__global__ __launch_bounds__(256, 1) void gemm_hmma(const __nv_bfloat16* __restrict__ Ah,
                                                    const __nv_bfloat16* __restrict__ Al,
                                                    const __nv_bfloat16* __restrict__ Bh,
                                                    const __nv_bfloat16* __restrict__ Bl,
                                                    float* __restrict__ C, int N) {
    extern __shared__ char smem[];
    const uint32_t sbase = smem_to_u32(smem);
    const int tid = threadIdx.x, wid = tid >> 5, lane = tid & 31;
    const int wm = wid & 1, wn = wid >> 1;          // 2 x 4 warp grid
    const int bm = blockIdx.y * 128, bn = blockIdx.x * 128;

    const __nv_bfloat16* srcs[4] = {
        Ah + (size_t)bm * GK, Al + (size_t)bm * GK,
        Bh + (size_t)bn * GK, Bl + (size_t)bn * GK };

    // stage loader: 4 tiles x 512 x 16B chunks, 8 chunks/thread
    auto stage_load = [&](int buf, int k0) {
        const uint32_t so = sbase + buf * STAGE_SB;
#pragma unroll
        for (int j = 0; j < 4; j++) {
            const __nv_bfloat16* src = srcs[j] + k0;
#pragma unroll
            for (int r = 0; r < 2; r++) {
                int c = tid + r * 256;
                int row = c >> 2, seg = c & 3;
                uint32_t d = so + (uint32_t)j * TILE_SB + (row * TSTRIDE + seg * 8) * 2;
                CP_ASYNC16(d, src + (size_t)row * GK + seg * 8);
            }
        }
        CP_COMMIT();
    };

    float acc[4][4][4];
#pragma unroll
    for (int i = 0; i < 4; i++)
#pragma unroll
        for (int j = 0; j < 4; j++)
#pragma unroll
            for (int r = 0; r < 4; r++) acc[i][j][r] = 0.f;

    stage_load(0, 0);
    stage_load(1, 32);

    // per-lane ldmatrix address components
    const int arow = (lane & 7) + ((lane >> 3) & 1) * 8;   // row within m16 block
    const int acol8 = ((lane >> 4) & 1) * 8;               // k-offset for A x4
    const int brow = lane & 7;                             // row within n8 block
    const int bcol8 = ((lane >> 3) & 1) * 8;               // k-offset for B x2

    for (int s = 0; s < NSTAGE; s++) {
        const int buf = s & 1;
        CP_WAIT1();
        __syncthreads();
        const uint32_t so = sbase + buf * STAGE_SB;
        const uint32_t aH = so, aL = so + TILE_SB, bH = so + 2*TILE_SB, bL = so + 3*TILE_SB;
#pragma unroll
        for (int kk = 0; kk < 2; kk++) {
            uint32_t ah[16], al[16], bh[8], bl[8];
            const int akc = kk * 16 + acol8;
            const int bkc = kk * 16 + bcol8;
#pragma unroll
            for (int mb = 0; mb < 4; mb++) {
                const uint32_t off = ((wm*64 + mb*16 + arow) * TSTRIDE + akc) * 2;
                LDSM4(ah[4*mb], ah[4*mb+1], ah[4*mb+2], ah[4*mb+3], aH + off);
                LDSM4(al[4*mb], al[4*mb+1], al[4*mb+2], al[4*mb+3], aL + off);
            }
#pragma unroll
            for (int nb = 0; nb < 4; nb++) {
                const uint32_t off = ((wn*32 + nb*8 + brow) * TSTRIDE + bkc) * 2;
                LDSM2(bh[2*nb], bh[2*nb+1], bH + off);
                LDSM2(bl[2*nb], bl[2*nb+1], bL + off);
            }
#pragma unroll
            for (int mb = 0; mb < 4; mb++)
#pragma unroll
                for (int nb = 0; nb < 4; nb++) {
                    MMA16816(acc[mb][nb], &ah[4*mb], &bh[2*nb]);
                    MMA16816(acc[mb][nb], &ah[4*mb], &bl[2*nb]);
                    MMA16816(acc[mb][nb], &al[4*mb], &bh[2*nb]);
                }
        }
        __syncthreads();
        if (s + 2 < NSTAGE) stage_load(buf, (s + 2) * 32);
    }
    CP_WAIT0();

    // epilogue: fragment layout c0,c1 -> (m=lane/4, n=2(lane%4)+{0,1}); c2,c3 -> m+8
    const int mrow = bm + wm*64 + (lane >> 2);
    const int ncol = bn + wn*32 + 2*(lane & 3);
#pragma unroll
    for (int mb = 0; mb < 4; mb++)
#pragma unroll
        for (int nb = 0; nb < 4; nb++) {
            float* p0 = C + (size_t)(mrow + mb*16)     * N + ncol + nb*8;
            float* p1 = C + (size_t)(mrow + mb*16 + 8) * N + ncol + nb*8;
            *(float2*)p0 = make_float2(acc[mb][nb][0], acc[mb][nb][1]);
            *(float2*)p1 = make_float2(acc[mb][nb][2], acc[mb][nb][3]);
        }
}

// ---------------- Phase A: per-chunk KV[f][e] and K1[f] sums (register-tiled GEMM) ----------------
__global__ __launch_bounds__(256) void chunk_kv_kernel() {
    extern __shared__ float sm[];
    float* ks2 = sm;              // [128][17] : k values + ones column
    float* vs  = sm + 128*17;     // [128][132] (padded)
    float* tA  = vs + 128*132;    // [16][128] : kf panel, layout [tt][f_local]
    const int bid = blockIdx.x;
    const int bh = bid / NC, c = bid % NC;
    const int b = bh / NH, h = bh % NH;
    const int t0c = c * CH;
    const int tid = threadIdx.x;
    const int tx = tid & 15, ty = tid >> 4;
    const size_t rowbase = (size_t)(b*T_ + t0c);

    for (int idx = tid; idx < 128*16; idx += 256) {
        int t = idx >> 4, i = idx & 15;
        ks2[t*17 + i] = g_qk[(rowbase + t)*NQK + 192 + h*DK + i];
    }
    for (int idx = tid; idx < 128; idx += 256) ks2[idx*17 + 16] = 1.f;
    for (int idx = tid; idx < 128*32; idx += 256) {
        int t = idx >> 5, e4 = (idx & 31) << 2;
        *(float4*)&vs[t*132 + e4] =
            *(const float4*)&g_v[(rowbase + t)*(NH*DV) + h*DV + e4];
    }
    __syncthreads();

    for (int fsub = 0; fsub < 3; fsub++) {
        const int fbase = fsub * 128;
        float acc[8][8];
#pragma unroll
        for (int i = 0; i < 8; i++)
#pragma unroll
            for (int j = 0; j < 8; j++) acc[i][j] = 0.f;

        for (int tp = 0; tp < 8; tp++) {
            const int t0 = tp * 16;
            for (int idx = tid; idx < 2048; idx += 256) {
                int tt = idx >> 7, fl = idx & 127;
                int f = fbase + fl;
                float val = 0.f;
                if (f < DF) {
                    int ia, ib; float sc; fdecomp(f, ia, ib, sc);
                    val = ks2[(t0+tt)*17 + ia] * ks2[(t0+tt)*17 + ib] * sc;
                }
                tA[tt*128 + fl] = val;
            }
            __syncthreads();
#pragma unroll
            for (int tt = 0; tt < 16; tt++) {
                float a[8], bb[8];
                *(float4*)(a)    = *(const float4*)&tA[tt*128 + ty*8];
                *(float4*)(a+4)  = *(const float4*)&tA[tt*128 + ty*8 + 4];
                *(float4*)(bb)   = *(const float4*)&vs[(t0+tt)*132 + tx*8];
                *(float4*)(bb+4) = *(const float4*)&vs[(t0+tt)*132 + tx*8 + 4];
#pragma unroll
                for (int i = 0; i < 8; i++)
#pragma unroll
                    for (int j = 0; j < 8; j++) acc[i][j] += a[i]*bb[j];
            }
            __syncthreads();
        }
#pragma unroll
        for (int i = 0; i < 8; i++) {
            int f = fbase + ty*8 + i;
            if (f >= DF) continue;
            size_t base = ((size_t)bid*DF + f)*DV + tx*8;
            *(float4*)&g_KV[base]   = make_float4(acc[i][0], acc[i][1], acc[i][2], acc[i][3]);
            *(float4*)&g_KV[base+4] = make_float4(acc[i][4], acc[i][5], acc[i][6], acc[i][7]);
        }
    }

    for (int f = tid; f < DF; f += 256) {
        int ia, ib; float sc; fdecomp(f, ia, ib, sc);
        float s = 0.f;
#pragma unroll 4
        for (int t = 0; t < 128; t++) s += ks2[t*17+ia]*ks2[t*17+ib];
        g_K1[(size_t)bid*DF + f] = s*sc;
    }
}

// ---------------- Phase B: exclusive prefix scan over chunks ----------------
__global__ __launch_bounds__(256) void scan_kernel() {
    const int bh = blockIdx.x;
    const int part = blockIdx.y;             // 0..17
    const int stride = 18*256;
    size_t baseKV = (size_t)bh*NC*DF*DV;
    for (int idx = part*256 + threadIdx.x; idx < DF*DV; idx += stride) {
        float prev = 0.f;
        size_t p = baseKV + idx;
#pragma unroll
        for (int cc = 0; cc < NC; cc++) {
            float tmp = g_KV[p]; g_KV[p] = prev; prev += tmp;
            p += (size_t)DF*DV;
        }
    }
    if (part == 0) {
        size_t baseK = (size_t)bh*NC*DF;
        for (int idx = threadIdx.x; idx < DF; idx += 256) {
            float prev = 0.f; size_t p = baseK + idx;
#pragma unroll
            for (int cc = 0; cc < NC; cc++) {
                float tmp = g_K1[p]; g_K1[p] = prev; prev += tmp; p += DF;
            }
        }
    }
}

// ---------------- Phase C: fused inter + intra chunk attention ----------------
__global__ __launch_bounds__(256) void attn_kernel() {
    extern __shared__ float sm[];
    float* qT2 = sm;                 // [17][128] q values (+ones row 16), f-major
    float* kT  = qT2 + 17*128;       // [16][128]
    float* Ss  = kT  + 16*128;       // [128][132] masked phi scores
    float* tA  = Ss  + 128*132;      // [16][128] qf tile (f-chunk)
    float* tB  = tA  + 16*128;       // [16][128] state / v tile
    float* stK = tB  + 16*128;       // [288] exclusive K1 state
    float* dsh = stK + 288;          // [128] denominators

    const int bid = blockIdx.x;
    const int bh = bid / NC, c = bid % NC;
    const int b = bh / NH, h = bh % NH;
    const int t0 = c * CH;
    const int tid = threadIdx.x;
    const int tx = tid & 15, ty = tid >> 4;
    const size_t rowbase = (size_t)(b*T_ + t0);

    for (int idx = tid; idx < 128*16; idx += 256) {
        int t = idx >> 4, i = idx & 15;
        qT2[i*128 + t] = g_qk[(rowbase + t)*NQK + h*DK + i];
        kT [i*128 + t] = g_qk[(rowbase + t)*NQK + 192 + h*DK + i];
    }
    for (int idx = tid; idx < 128; idx += 256) qT2[16*128 + idx] = 1.f;
    for (int f = tid; f < DF; f += 256) stK[f] = g_K1[(size_t)bid*DF + f];
    __syncthreads();

    // ---- S[t][s] = phi(q_t . k_s), causal mask; phi(x)=1+x/4+x^2/32 ----
    {
        float sacc[8][8];
#pragma unroll
        for (int i = 0; i < 8; i++)
#pragma unroll
            for (int j = 0; j < 8; j++) sacc[i][j] = 0.f;
#pragma unroll
        for (int kk = 0; kk < 16; kk++) {
            float a[8], bb[8];
            *(float4*)(a)    = *(const float4*)&qT2[kk*128 + ty*8];
            *(float4*)(a+4)  = *(const float4*)&qT2[kk*128 + ty*8 + 4];
            *(float4*)(bb)   = *(const float4*)&kT [kk*128 + tx*8];
            *(float4*)(bb+4) = *(const float4*)&kT [kk*128 + tx*8 + 4];
#pragma unroll
            for (int i = 0; i < 8; i++)
#pragma unroll
                for (int j = 0; j < 8; j++) sacc[i][j] += a[i]*bb[j];
        }
#pragma unroll
        for (int i = 0; i < 8; i++) {
            int t = ty*8 + i;
#pragma unroll
            for (int j = 0; j < 8; j++) {
                int s = tx*8 + j;
                float d = sacc[i][j];
                Ss[t*132 + s] = (s <= t) ? (1.f + 0.25f*d + 0.03125f*d*d) : 0.f;
            }
        }
    }
    __syncthreads();

    // ---- denominators: qf . stateK  +  rowsum(S) + EPS ----
    if (tid < 128) {
        const int t = tid;
        float qv[16];
#pragma unroll
        for (int i = 0; i < 16; i++) qv[i] = qT2[i*128 + t];
        float dacc = stK[0];
#pragma unroll
        for (int i = 0; i < 16; i++) dacc += qv[i]*0.5f*stK[1+i];
#pragma unroll
        for (int i = 0; i < 16; i++) {
            float qi = qv[i]*INV4R2;
#pragma unroll
            for (int j = 0; j < 16; j++)
                dacc += qi*qv[j]*stK[17 + i*16 + j];
        }
        float di = 0.f;
        for (int s = 0; s < 128; s++) di += Ss[t*132 + s];
        dsh[t] = dacc + di + 1e-12f;
    }
    __syncthreads();

    float acc[8][8];
#pragma unroll
    for (int i = 0; i < 8; i++)
#pragma unroll
        for (int j = 0; j < 8; j++) acc[i][j] = 0.f;

    // ---- inter-chunk: y += qf @ stateKV  (18 f-chunks of 16, padded) ----
    for (int fc = 0; fc < 18; fc++) {
        const int f0 = fc * 16;
        for (int idx = tid; idx < 2048; idx += 256) {
            int kk = idx >> 7, t = idx & 127;
            int f = f0 + kk;
            float val = 0.f;
            if (f < DF) {
                int ia, ib; float scl; fdecomp(f, ia, ib, scl);
                val = qT2[ia*128 + t] * qT2[ib*128 + t] * scl;
            }
            tA[kk*128 + t] = val;
        }
        for (int idx = tid; idx < 512; idx += 256) {
            int kk = idx >> 5, e4 = (idx & 31) << 2;
            int f = f0 + kk;
            float4 v = make_float4(0.f,0.f,0.f,0.f);
            if (f < DF) v = *(const float4*)&g_KV[((size_t)bid*DF + f)*DV + e4];
            *(float4*)&tB[kk*128 + e4] = v;
        }
        __syncthreads();
#pragma unroll
        for (int kk = 0; kk < 16; kk++) {
            float a[8], bb[8];
            *(float4*)(a)    = *(const float4*)&tA[kk*128 + ty*8];
            *(float4*)(a+4)  = *(const float4*)&tA[kk*128 + ty*8 + 4];
            *(float4*)(bb)   = *(const float4*)&tB[kk*128 + tx*8];
            *(float4*)(bb+4) = *(const float4*)&tB[kk*128 + tx*8 + 4];
#pragma unroll
            for (int i = 0; i < 8; i++)
#pragma unroll
                for (int j = 0; j < 8; j++) acc[i][j] += a[i]*bb[j];
        }
        __syncthreads();
    }

    // ---- intra-chunk: y += S @ v  (8 s-chunks of 16) ----
    for (int scn = 0; scn < 8; scn++) {
        const int s0 = scn * 16;
        for (int idx = tid; idx < 512; idx += 256) {
            int kk = idx >> 5, e4 = (idx & 31) << 2;
            *(float4*)&tB[kk*128 + e4] =
                *(const float4*)&g_v[(rowbase + s0 + kk)*(NH*DV) + h*DV + e4];
        }
        __syncthreads();
#pragma unroll
        for (int kk = 0; kk < 16; kk++) {
            float bb[8];
            *(float4*)(bb)   = *(const float4*)&tB[kk*128 + tx*8];
            *(float4*)(bb+4) = *(const float4*)&tB[kk*128 + tx*8 + 4];
#pragma unroll
            for (int i = 0; i < 8; i++) {
                float a = Ss[(ty*8+i)*132 + s0 + kk];
#pragma unroll
                for (int j = 0; j < 8; j++) acc[i][j] += a*bb[j];
            }
        }
        __syncthreads();
    }

    // ---- epilogue: divide by den, write y ----
#pragma unroll
    for (int i = 0; i < 8; i++) {
        int t = ty*8 + i;
        float r = 1.f / dsh[t];
        size_t row = (rowbase + t)*(NH*DV) + h*DV + tx*8;
        *(float4*)&g_y[row]   = make_float4(acc[i][0]*r, acc[i][1]*r, acc[i][2]*r, acc[i][3]*r);
        *(float4*)&g_y[row+4] = make_float4(acc[i][4]*r, acc[i][5]*r, acc[i][6]*r, acc[i][7]*r);
    }
}

// ---------------- launch ----------------
extern "C" void kernel_launch(void* const* d_in, const int* in_sizes, int n_in,
                              void* d_out, int out_size) {
    const float* hs = (const float*)d_in[0];
    const float* Wq = (const float*)d_in[1];
    const float* Wk = (const float*)d_in[2];
    const float* Wv = (const float*)d_in[3];
    const float* Wo = (const float*)d_in[4];
    float* out = (float*)d_out;

    float *qk, *v, *y;
    cudaGetSymbolAddress((void**)&qk, g_qk);
    cudaGetSymbolAddress((void**)&v,  g_v);
    cudaGetSymbolAddress((void**)&y,  g_y);
    __nv_bfloat16 *hsH, *hsL, *wqkH, *wqkL, *wvH, *wvL, *woH, *woL, *yH, *yL;
    cudaGetSymbolAddress((void**)&hsH,  g_hsH);  cudaGetSymbolAddress((void**)&hsL,  g_hsL);
    cudaGetSymbolAddress((void**)&wqkH, g_wqkH); cudaGetSymbolAddress((void**)&wqkL, g_wqkL);
    cudaGetSymbolAddress((void**)&wvH,  g_wvH);  cudaGetSymbolAddress((void**)&wvL,  g_wvL);
    cudaGetSymbolAddress((void**)&woH,  g_woH);  cudaGetSymbolAddress((void**)&woL,  g_woL);
    cudaGetSymbolAddress((void**)&yH,   g_yH);   cudaGetSymbolAddress((void**)&yL,   g_yL);

    const int SMEM_A = (128*17 + 128*132 + 16*128) * 4;           // 84480 B
    const int SMEM_C = (17*128 + 16*128 + 128*132 + 16*128 + 16*128 + 288 + 128) * 4; // 102528 B
    cudaFuncSetAttribute(chunk_kv_kernel, cudaFuncAttributeMaxDynamicSharedMemorySize, SMEM_A);
    cudaFuncSetAttribute(attn_kernel,     cudaFuncAttributeMaxDynamicSharedMemorySize, SMEM_C);
    cudaFuncSetAttribute(gemm_hmma,       cudaFuncAttributeMaxDynamicSharedMemorySize, SMEM_G);

    dim3 thr(256);
    // split-converts
    conv_split<<<296, thr>>>(hs, hsH, hsL, MROWS*HID);
    conv_split<<<148, thr>>>(Wq, wqkH, wqkL, 192*HID);
    conv_split<<<148, thr>>>(Wk, wqkH + 192*HID, wqkL + 192*HID, 192*HID);
    conv_split<<<296, thr>>>(Wv, wvH, wvL, HID*HID);
    conv_split<<<296, thr>>>(Wo, woH, woL, HID*HID);

    // tensor-core (HMMA) projections
    gemm_hmma<<<dim3(NQK/128, MROWS/128), thr, SMEM_G>>>(hsH, hsL, wqkH, wqkL, qk, NQK);
    gemm_hmma<<<dim3(HID/128, MROWS/128), thr, SMEM_G>>>(hsH, hsL, wvH, wvL, v, HID);

    chunk_kv_kernel<<<BH*NC, thr, SMEM_A>>>();
    scan_kernel<<<dim3(BH, 18), thr>>>();
    attn_kernel<<<BH*NC, thr, SMEM_C>>>();

    // out = y @ Wo^T on tensor cores
    conv_split<<<296, thr>>>(y, yH, yL, MROWS*HID);
    gemm_hmma<<<dim3(HID/128, MROWS/128), thr, SMEM_G>>>(yH, yL, woH, woL, out, HID);
}

// round 9
// speedup vs baseline: 2.4029x; 1.0919x over previous
#include <cuda_runtime.h>
#include <cuda_bf16.h>
#include <cstdint>
#include <math.h>

// Problem constants
#define B_    2
#define T_    2048
#define HID   1536
#define NH    12
#define DK    16
#define DV    128
#define DF    273          // 1 + 16 + 256 taylor features
#define CH    128          // chunk length
#define NC    (T_/CH)      // 16 chunks
#define BH    (B_*NH)      // 24
#define MROWS (B_*T_)      // 4096
#define NQK   384          // q|k combined output cols (192+192)
#define GK    1536

#define INV4R2 0.17677669529663687f   // 1/(4*sqrt(2))

// ---------------- scratch (static device allocations; no cudaMalloc) ----------------
__device__ float g_qk[MROWS*NQK];        // [b*t][ q(0..191) | k(192..383) ]
__device__ float g_v [MROWS*NH*DV];      // [b*t][H*dv]
__device__ float g_KV[(size_t)BH*NC*DF*DV];
__device__ float g_K1[(size_t)BH*NC*DF];

// bf16 split buffers
__device__ __nv_bfloat16 g_hsH[MROWS*HID], g_hsL[MROWS*HID];
__device__ __nv_bfloat16 g_wqkH[NQK*HID],  g_wqkL[NQK*HID];
__device__ __nv_bfloat16 g_wvH[HID*HID],   g_wvL[HID*HID];
__device__ __nv_bfloat16 g_woH[HID*HID],   g_woL[HID*HID];
__device__ __nv_bfloat16 g_yH[MROWS*HID],  g_yL[MROWS*HID];

// ---------------- portable PTX helpers (valid on compute_103 base target) ----------------
__device__ __forceinline__ uint32_t smem_to_u32(const void* p) {
    uint32_t a;
    asm("{ .reg .u64 t; cvta.to.shared.u64 t, %1; cvt.u32.u64 %0, t; }" : "=r"(a) : "l"(p));
    return a;
}
#define CP_ASYNC16(dst, src) \
    asm volatile("cp.async.cg.shared.global [%0], [%1], 16;" :: "r"(dst), "l"(src) : "memory")
#define CP_COMMIT() asm volatile("cp.async.commit_group;" ::: "memory")
#define CP_WAIT1()  asm volatile("cp.async.wait_group 1;" ::: "memory")
#define CP_WAIT0()  asm volatile("cp.async.wait_group 0;" ::: "memory")

#define LDSM4(r0, r1, r2, r3, addr) \
    asm volatile("ldmatrix.sync.aligned.m8n8.x4.shared.b16 {%0,%1,%2,%3}, [%4];" \
        : "=r"(r0), "=r"(r1), "=r"(r2), "=r"(r3) : "r"(addr))
#define LDSM2(r0, r1, addr) \
    asm volatile("ldmatrix.sync.aligned.m8n8.x2.shared.b16 {%0,%1}, [%2];" \
        : "=r"(r0), "=r"(r1) : "r"(addr))

#define MMA16816(c, a, b) \
    asm volatile("mma.sync.aligned.m16n8k16.row.col.f32.bf16.bf16.f32 " \
        "{%0,%1,%2,%3}, {%4,%5,%6,%7}, {%8,%9}, {%0,%1,%2,%3};" \
        : "+f"((c)[0]), "+f"((c)[1]), "+f"((c)[2]), "+f"((c)[3]) \
        : "r"((a)[0]), "r"((a)[1]), "r"((a)[2]), "r"((a)[3]), "r"((b)[0]), "r"((b)[1]))

__device__ __forceinline__ void split2(float x, __nv_bfloat16& h, __nv_bfloat16& l) {
    h = __float2bfloat16(x);
    l = __float2bfloat16(x - __bfloat162float(h));
}

// feature f -> (ia, ib, scale) with virtual index 16 == constant 1
__device__ __forceinline__ void fdecomp(int f, int& ia, int& ib, float& sc) {
    if (f == 0)      { ia = 16; ib = 16; sc = 1.f; }
    else if (f < 17) { ia = f - 1; ib = 16; sc = 0.5f; }
    else { int p = f - 17; ia = p >> 4; ib = p & 15; sc = INV4R2; }
}

// ---------------- fused split-convert: all inputs -> (bf16 hi, bf16 lo) ----------------
#define N_HS  (MROWS*HID)
#define N_W1  (192*HID)
#define N_WV  (HID*HID)
__global__ __launch_bounds__(256) void conv_all(const float* __restrict__ hs,
                                                const float* __restrict__ Wq,
                                                const float* __restrict__ Wk,
                                                const float* __restrict__ Wv,
                                                const float* __restrict__ Wo) {
    const int total = N_HS + 2*N_W1 + 2*N_WV;
    for (int i = blockIdx.x*256 + threadIdx.x; i < total; i += gridDim.x*256) {
        float x; __nv_bfloat16 *ph, *pl; int off;
        int j = i;
        if (j < N_HS) { x = hs[j]; ph = g_hsH; pl = g_hsL; off = j; }
        else {
            j -= N_HS;
            if (j < N_W1) { x = Wq[j]; ph = g_wqkH; pl = g_wqkL; off = j; }
            else {
                j -= N_W1;
                if (j < N_W1) { x = Wk[j]; ph = g_wqkH; pl = g_wqkL; off = j + N_W1; }
                else {
                    j -= N_W1;
                    if (j < N_WV) { x = Wv[j]; ph = g_wvH; pl = g_wvL; off = j; }
                    else { j -= N_WV; x = Wo[j]; ph = g_woH; pl = g_woL; off = j; }
                }
            }
        }
        __nv_bfloat16 h, l; split2(x, h, l);
        ph[off] = h; pl[off] = l;
    }
}

// ---------------- HMMA split-bf16 GEMM: C[M,N] = A[M,K]@B[N,K]^T ----------------
#define TSTRIDE 40
#define TILE_SB (128*TSTRIDE*2)
#define STAGE_SB (4*TILE_SB)
#define SMEM_G  (2*STAGE_SB)           // 81920 B
#define NSTAGE  (GK/32)                // 48

__global__ __launch_bounds__(256, 1) void gemm_hmma(const __nv_bfloat16* __restrict__ Ah,
                                                    const __nv_bfloat16* __restrict__ Al,
                                                    const __nv_bfloat16* __restrict__ Bh,
                                                    const __nv_bfloat16* __restrict__ Bl,
                                                    float* __restrict__ C, int N) {
    extern __shared__ char smem[];
    const uint32_t sbase = smem_to_u32(smem);
    const int tid = threadIdx.x, wid = tid >> 5, lane = tid & 31;
    const int wm = wid & 1, wn = wid >> 1;
    const int bm = blockIdx.y * 128, bn = blockIdx.x * 128;

    const __nv_bfloat16* srcs[4] = {
        Ah + (size_t)bm * GK, Al + (size_t)bm * GK,
        Bh + (size_t)bn * GK, Bl + (size_t)bn * GK };

    auto stage_load = [&](int buf, int k0) {
        const uint32_t so = sbase + buf * STAGE_SB;
#pragma unroll
        for (int j = 0; j < 4; j++) {
            const __nv_bfloat16* src = srcs[j] + k0;
#pragma unroll
            for (int r = 0; r < 2; r++) {
                int c = tid + r * 256;
                int row = c >> 2, seg = c & 3;
                uint32_t d = so + (uint32_t)j * TILE_SB + (row * TSTRIDE + seg * 8) * 2;
                CP_ASYNC16(d, src + (size_t)row * GK + seg * 8);
            }
        }
        CP_COMMIT();
    };

    float acc[4][4][4];
#pragma unroll
    for (int i = 0; i < 4; i++)
#pragma unroll
        for (int j = 0; j < 4; j++)
#pragma unroll
            for (int r = 0; r < 4; r++) acc[i][j][r] = 0.f;

    stage_load(0, 0);
    stage_load(1, 32);

    const int arow = (lane & 7) + ((lane >> 3) & 1) * 8;
    const int acol8 = ((lane >> 4) & 1) * 8;
    const int brow = lane & 7;
    const int bcol8 = ((lane >> 3) & 1) * 8;

    for (int s = 0; s < NSTAGE; s++) {
        const int buf = s & 1;
        CP_WAIT1();
        __syncthreads();
        const uint32_t so = sbase + buf * STAGE_SB;
        const uint32_t aH = so, aL = so + TILE_SB, bH = so + 2*TILE_SB, bL = so + 3*TILE_SB;
#pragma unroll
        for (int kk = 0; kk < 2; kk++) {
            uint32_t ah[16], al[16], bh[8], bl[8];
            const int akc = kk * 16 + acol8;
            const int bkc = kk * 16 + bcol8;
#pragma unroll
            for (int mb = 0; mb < 4; mb++) {
                const uint32_t off = ((wm*64 + mb*16 + arow) * TSTRIDE + akc) * 2;
                LDSM4(ah[4*mb], ah[4*mb+1], ah[4*mb+2], ah[4*mb+3], aH + off);
                LDSM4(al[4*mb], al[4*mb+1], al[4*mb+2], al[4*mb+3], aL + off);
            }
#pragma unroll
            for (int nb = 0; nb < 4; nb++) {
                const uint32_t off = ((wn*32 + nb*8 + brow) * TSTRIDE + bkc) * 2;
                LDSM2(bh[2*nb], bh[2*nb+1], bH + off);
                LDSM2(bl[2*nb], bl[2*nb+1], bL + off);
            }
#pragma unroll
            for (int mb = 0; mb < 4; mb++)
#pragma unroll
                for (int nb = 0; nb < 4; nb++) {
                    MMA16816(acc[mb][nb], &ah[4*mb], &bh[2*nb]);
                    MMA16816(acc[mb][nb], &ah[4*mb], &bl[2*nb]);
                    MMA16816(acc[mb][nb], &al[4*mb], &bh[2*nb]);
                }
        }
        __syncthreads();
        if (s + 2 < NSTAGE) stage_load(buf, (s + 2) * 32);
    }
    CP_WAIT0();

    const int mrow = bm + wm*64 + (lane >> 2);
    const int ncol = bn + wn*32 + 2*(lane & 3);
#pragma unroll
    for (int mb = 0; mb < 4; mb++)
#pragma unroll
        for (int nb = 0; nb < 4; nb++) {
            float* p0 = C + (size_t)(mrow + mb*16)     * N + ncol + nb*8;
            float* p1 = C + (size_t)(mrow + mb*16 + 8) * N + ncol + nb*8;
            *(float2*)p0 = make_float2(acc[mb][nb][0], acc[mb][nb][1]);
            *(float2*)p1 = make_float2(acc[mb][nb][2], acc[mb][nb][3]);
        }
}

// ---------------- Phase A: per-chunk KV[f][e] sums via HMMA ----------------
// KV[f][e] = sum_t kf[f][t]*v[t][e].  A = kf [f][t] (row-major, k=t), B = vT [e][t].
// smem: ks2 [128][17] fp32 | vTH/vTL [128][136] bf16 | kfH/kfL [96][136] bf16
#define CKV_VST 136
#define SMEM_A2 (128*17*4 + 2*(128*CKV_VST*2) + 2*(96*CKV_VST*2))   // 130560 B

__global__ __launch_bounds__(256, 1) void chunk_kv_kernel() {
    extern __shared__ char smraw[];
    float* ks2 = (float*)smraw;                                  // [128][17]
    __nv_bfloat16* vTH = (__nv_bfloat16*)(smraw + 128*17*4);     // [128][136]
    __nv_bfloat16* vTL = vTH + 128*CKV_VST;
    __nv_bfloat16* kfH = vTL + 128*CKV_VST;                      // [96][136]
    __nv_bfloat16* kfL = kfH + 96*CKV_VST;
    const uint32_t u_vTH = smem_to_u32(vTH), u_vTL = smem_to_u32(vTL);
    const uint32_t u_kfH = smem_to_u32(kfH), u_kfL = smem_to_u32(kfL);

    const int bid = blockIdx.x;
    const int bh = bid / NC, c = bid % NC;
    const int b = bh / NH, h = bh % NH;
    const int tid = threadIdx.x, wid = tid >> 5, lane = tid & 31;
    const int wm = wid & 1, wn = wid >> 1;
    const size_t rowbase = (size_t)(b*T_ + c*CH);

    // load k (+ones)
    for (int idx = tid; idx < 128*16; idx += 256) {
        int t = idx >> 4, i = idx & 15;
        ks2[t*17 + i] = g_qk[(rowbase + t)*NQK + 192 + h*DK + i];
    }
    for (int idx = tid; idx < 128; idx += 256) ks2[idx*17 + 16] = 1.f;

    // stage vT: [e][t] split bf16 (coalesced gmem read over e)
    for (int idx = tid; idx < 128*128; idx += 256) {
        int t = idx >> 7, e = idx & 127;
        float x = g_v[(rowbase + t)*(NH*DV) + h*DV + e];
        __nv_bfloat16 hh, ll; split2(x, hh, ll);
        vTH[e*CKV_VST + t] = hh; vTL[e*CKV_VST + t] = ll;
    }
    __syncthreads();

    const int arow = (lane & 7) + ((lane >> 3) & 1) * 8;
    const int acol8 = ((lane >> 4) & 1) * 8;
    const int brow = lane & 7;
    const int bcol8 = ((lane >> 3) & 1) * 8;

    for (int fsub = 0; fsub < 3; fsub++) {
        // stage kf tile [96][128] split bf16
        for (int idx = tid; idx < 96*128; idx += 256) {
            int fl = idx >> 7, t = idx & 127;
            int f = fsub*96 + fl;
            float val = 0.f;
            if (f < DF) {
                int ia, ib; float sc; fdecomp(f, ia, ib, sc);
                val = ks2[t*17 + ia] * ks2[t*17 + ib] * sc;
            }
            __nv_bfloat16 hh, ll; split2(val, hh, ll);
            kfH[fl*CKV_VST + t] = hh; kfL[fl*CKV_VST + t] = ll;
        }
        __syncthreads();

        float acc[3][4][4];
#pragma unroll
        for (int i = 0; i < 3; i++)
#pragma unroll
            for (int j = 0; j < 4; j++)
#pragma unroll
                for (int r = 0; r < 4; r++) acc[i][j][r] = 0.f;

#pragma unroll
        for (int kc = 0; kc < 8; kc++) {
            const int t0 = kc * 16;
            uint32_t ah[12], al[12], bhr[8], blr[8];
#pragma unroll
            for (int mb = 0; mb < 3; mb++) {
                const uint32_t off = ((wm*48 + mb*16 + arow) * CKV_VST + t0 + acol8) * 2;
                LDSM4(ah[4*mb], ah[4*mb+1], ah[4*mb+2], ah[4*mb+3], u_kfH + off);
                LDSM4(al[4*mb], al[4*mb+1], al[4*mb+2], al[4*mb+3], u_kfL + off);
            }
#pragma unroll
            for (int nb = 0; nb < 4; nb++) {
                const uint32_t off = ((wn*32 + nb*8 + brow) * CKV_VST + t0 + bcol8) * 2;
                LDSM2(bhr[2*nb], bhr[2*nb+1], u_vTH + off);
                LDSM2(blr[2*nb], blr[2*nb+1], u_vTL + off);
            }
#pragma unroll
            for (int mb = 0; mb < 3; mb++)
#pragma unroll
                for (int nb = 0; nb < 4; nb++) {
                    MMA16816(acc[mb][nb], &ah[4*mb], &bhr[2*nb]);
                    MMA16816(acc[mb][nb], &ah[4*mb], &blr[2*nb]);
                    MMA16816(acc[mb][nb], &al[4*mb], &bhr[2*nb]);
                }
        }

        // epilogue
        const int e0 = wn*32 + 2*(lane & 3);
#pragma unroll
        for (int mb = 0; mb < 3; mb++) {
            int f0 = fsub*96 + wm*48 + mb*16 + (lane >> 2);
#pragma unroll
            for (int nb = 0; nb < 4; nb++) {
                if (f0 < DF)
                    *(float2*)&g_KV[((size_t)bid*DF + f0)*DV + e0 + nb*8] =
                        make_float2(acc[mb][nb][0], acc[mb][nb][1]);
                if (f0 + 8 < DF)
                    *(float2*)&g_KV[((size_t)bid*DF + f0 + 8)*DV + e0 + nb*8] =
                        make_float2(acc[mb][nb][2], acc[mb][nb][3]);
            }
        }
        __syncthreads();
    }

    // K1[f] = sum_t kf[f][t]  (FFMA, tiny)
    for (int f = tid; f < DF; f += 256) {
        int ia, ib; float sc; fdecomp(f, ia, ib, sc);
        float s = 0.f;
#pragma unroll 4
        for (int t = 0; t < 128; t++) s += ks2[t*17+ia]*ks2[t*17+ib];
        g_K1[(size_t)bid*DF + f] = s*sc;
    }
}

// ---------------- Phase B: exclusive prefix scan over chunks ----------------
__global__ __launch_bounds__(256) void scan_kernel() {
    const int bh = blockIdx.x;
    const int part = blockIdx.y;             // 0..17
    const int stride = 18*256;
    size_t baseKV = (size_t)bh*NC*DF*DV;
    for (int idx = part*256 + threadIdx.x; idx < DF*DV; idx += stride) {
        float prev = 0.f;
        size_t p = baseKV + idx;
#pragma unroll
        for (int cc = 0; cc < NC; cc++) {
            float tmp = g_KV[p]; g_KV[p] = prev; prev += tmp;
            p += (size_t)DF*DV;
        }
    }
    if (part == 0) {
        size_t baseK = (size_t)bh*NC*DF;
        for (int idx = threadIdx.x; idx < DF; idx += 256) {
            float prev = 0.f; size_t p = baseK + idx;
#pragma unroll
            for (int cc = 0; cc < NC; cc++) {
                float tmp = g_K1[p]; g_K1[p] = prev; prev += tmp; p += DF;
            }
        }
    }
}

// ---------------- Phase C: fused inter + intra attention via HMMA ----------------
// y[t][e] = qf[t][:288] @ state + S[t][:128] @ v ; then /den, write split bf16 yH/yL.
// smem fp32: qT2 [17][128], kT [16][128], Ss [128][132], stK [288], dsh [128]
// smem bf16: aH/aL [128][24], bH/bL [128][24]
#define ATT_AST 24
#define ATT_F32 (17*128 + 16*128 + 128*132 + 288 + 128)
#define SMEM_C2 (ATT_F32*4 + 4*(128*ATT_AST*2))   // 86144 + 24576 = 110720 B

__global__ __launch_bounds__(256, 1) void attn_kernel() {
    extern __shared__ char smraw[];
    float* qT2 = (float*)smraw;          // [17][128]
    float* kT  = qT2 + 17*128;           // [16][128]
    float* Ss  = kT  + 16*128;           // [128][132]
    float* stK = Ss  + 128*132;          // [288]
    float* dsh = stK + 288;              // [128]
    __nv_bfloat16* aHp = (__nv_bfloat16*)(smraw + ATT_F32*4);
    __nv_bfloat16* aLp = aHp + 128*ATT_AST;
    __nv_bfloat16* bHp = aLp + 128*ATT_AST;
    __nv_bfloat16* bLp = bHp + 128*ATT_AST;
    const uint32_t u_aH = smem_to_u32(aHp), u_aL = smem_to_u32(aLp);
    const uint32_t u_bH = smem_to_u32(bHp), u_bL = smem_to_u32(bLp);

    const int bid = blockIdx.x;
    const int bh = bid / NC, c = bid % NC;
    const int b = bh / NH, h = bh % NH;
    const int tid = threadIdx.x, wid = tid >> 5, lane = tid & 31;
    const int wm = wid & 1, wn = wid >> 1;
    const int tx = tid & 15, ty = tid >> 4;
    const size_t rowbase = (size_t)(b*T_ + c*CH);

    for (int idx = tid; idx < 128*16; idx += 256) {
        int t = idx >> 4, i = idx & 15;
        qT2[i*128 + t] = g_qk[(rowbase + t)*NQK + h*DK + i];
        kT [i*128 + t] = g_qk[(rowbase + t)*NQK + 192 + h*DK + i];
    }
    for (int idx = tid; idx < 128; idx += 256) qT2[16*128 + idx] = 1.f;
    for (int f = tid; f < DF; f += 256) stK[f] = g_K1[(size_t)bid*DF + f];
    __syncthreads();

    // ---- S[t][s] = phi(q_t . k_s), causal; phi(x)=1+x/4+x^2/32 (fp32) ----
    {
        float sacc[8][8];
#pragma unroll
        for (int i = 0; i < 8; i++)
#pragma unroll
            for (int j = 0; j < 8; j++) sacc[i][j] = 0.f;
#pragma unroll
        for (int kk = 0; kk < 16; kk++) {
            float a[8], bb[8];
            *(float4*)(a)    = *(const float4*)&qT2[kk*128 + ty*8];
            *(float4*)(a+4)  = *(const float4*)&qT2[kk*128 + ty*8 + 4];
            *(float4*)(bb)   = *(const float4*)&kT [kk*128 + tx*8];
            *(float4*)(bb+4) = *(const float4*)&kT [kk*128 + tx*8 + 4];
#pragma unroll
            for (int i = 0; i < 8; i++)
#pragma unroll
                for (int j = 0; j < 8; j++) sacc[i][j] += a[i]*bb[j];
        }
#pragma unroll
        for (int i = 0; i < 8; i++) {
            int t = ty*8 + i;
#pragma unroll
            for (int j = 0; j < 8; j++) {
                int s = tx*8 + j;
                float d = sacc[i][j];
                Ss[t*132 + s] = (s <= t) ? (1.f + 0.25f*d + 0.03125f*d*d) : 0.f;
            }
        }
    }
    __syncthreads();

    // ---- denominators ----
    if (tid < 128) {
        const int t = tid;
        float qv[16];
#pragma unroll
        for (int i = 0; i < 16; i++) qv[i] = qT2[i*128 + t];
        float dacc = stK[0];
#pragma unroll
        for (int i = 0; i < 16; i++) dacc += qv[i]*0.5f*stK[1+i];
#pragma unroll
        for (int i = 0; i < 16; i++) {
            float qi = qv[i]*INV4R2;
#pragma unroll
            for (int j = 0; j < 16; j++)
                dacc += qi*qv[j]*stK[17 + i*16 + j];
        }
        float di = 0.f;
        for (int s = 0; s < 128; s++) di += Ss[t*132 + s];
        dsh[t] = dacc + di + 1e-12f;
    }

    const int arow = (lane & 7) + ((lane >> 3) & 1) * 8;
    const int acol8 = ((lane >> 4) & 1) * 8;
    const int brow = lane & 7;
    const int bcol8 = ((lane >> 3) & 1) * 8;

    float acc[4][4][4];
#pragma unroll
    for (int i = 0; i < 4; i++)
#pragma unroll
        for (int j = 0; j < 4; j++)
#pragma unroll
            for (int r = 0; r < 4; r++) acc[i][j][r] = 0.f;

    // ---- 26 k-chunks: 18 inter (qf @ state) + 8 intra (S @ v) ----
    for (int ch = 0; ch < 26; ch++) {
        __syncthreads();
        if (ch < 18) {
            const int f0 = ch * 16;
            // A: qf tile [t][kk]
            for (int idx = tid; idx < 2048; idx += 256) {
                int t = idx >> 4, kk = idx & 15;
                int f = f0 + kk;
                float val = 0.f;
                if (f < DF) {
                    int ia, ib; float sc; fdecomp(f, ia, ib, sc);
                    val = qT2[ia*128 + t] * qT2[ib*128 + t] * sc;
                }
                __nv_bfloat16 hh, ll; split2(val, hh, ll);
                aHp[t*ATT_AST + kk] = hh; aLp[t*ATT_AST + kk] = ll;
            }
            // B: state tile [e][kk] from g_KV (coalesced over e)
            for (int idx = tid; idx < 2048; idx += 256) {
                int kk = idx >> 7, e = idx & 127;
                int f = f0 + kk;
                float val = (f < DF) ? g_KV[((size_t)bid*DF + f)*DV + e] : 0.f;
                __nv_bfloat16 hh, ll; split2(val, hh, ll);
                bHp[e*ATT_AST + kk] = hh; bLp[e*ATT_AST + kk] = ll;
            }
        } else {
            const int s0 = (ch - 18) * 16;
            // A: S tile [t][kk]
            for (int idx = tid; idx < 2048; idx += 256) {
                int t = idx >> 4, kk = idx & 15;
                float val = Ss[t*132 + s0 + kk];
                __nv_bfloat16 hh, ll; split2(val, hh, ll);
                aHp[t*ATT_AST + kk] = hh; aLp[t*ATT_AST + kk] = ll;
            }
            // B: v tile [e][kk]
            for (int idx = tid; idx < 2048; idx += 256) {
                int kk = idx >> 7, e = idx & 127;
                float val = g_v[(rowbase + s0 + kk)*(NH*DV) + h*DV + e];
                __nv_bfloat16 hh, ll; split2(val, hh, ll);
                bHp[e*ATT_AST + kk] = hh; bLp[e*ATT_AST + kk] = ll;
            }
        }
        __syncthreads();

        uint32_t ah[16], al[16], bhr[8], blr[8];
#pragma unroll
        for (int mb = 0; mb < 4; mb++) {
            const uint32_t off = ((wm*64 + mb*16 + arow) * ATT_AST + acol8) * 2;
            LDSM4(ah[4*mb], ah[4*mb+1], ah[4*mb+2], ah[4*mb+3], u_aH + off);
            LDSM4(al[4*mb], al[4*mb+1], al[4*mb+2], al[4*mb+3], u_aL + off);
        }
#pragma unroll
        for (int nb = 0; nb < 4; nb++) {
            const uint32_t off = ((wn*32 + nb*8 + brow) * ATT_AST + bcol8) * 2;
            LDSM2(bhr[2*nb], bhr[2*nb+1], u_bH + off);
            LDSM2(blr[2*nb], blr[2*nb+1], u_bL + off);
        }
#pragma unroll
        for (int mb = 0; mb < 4; mb++)
#pragma unroll
            for (int nb = 0; nb < 4; nb++) {
                MMA16816(acc[mb][nb], &ah[4*mb], &bhr[2*nb]);
                MMA16816(acc[mb][nb], &ah[4*mb], &blr[2*nb]);
                MMA16816(acc[mb][nb], &al[4*mb], &bhr[2*nb]);
            }
    }
    __syncthreads();

    // ---- epilogue: divide by den, write split bf16 y ----
    const int e0 = wn*32 + 2*(lane & 3);
#pragma unroll
    for (int mb = 0; mb < 4; mb++) {
        int t0 = wm*64 + mb*16 + (lane >> 2);
#pragma unroll
        for (int half = 0; half < 2; half++) {
            int t = t0 + half*8;
            float r = 1.f / dsh[t];
            size_t row = (rowbase + t)*HID + h*DV;
#pragma unroll
            for (int nb = 0; nb < 4; nb++) {
                float y0 = acc[mb][nb][2*half]   * r;
                float y1 = acc[mb][nb][2*half+1] * r;
                __nv_bfloat16 h0, l0, h1, l1;
                split2(y0, h0, l0); split2(y1, h1, l1);
                g_yH[row + e0 + nb*8]     = h0;  g_yL[row + e0 + nb*8]     = l0;
                g_yH[row + e0 + nb*8 + 1] = h1;  g_yL[row + e0 + nb*8 + 1] = l1;
            }
        }
    }
}

// ---------------- launch ----------------
extern "C" void kernel_launch(void* const* d_in, const int* in_sizes, int n_in,
                              void* d_out, int out_size) {
    const float* hs = (const float*)d_in[0];
    const float* Wq = (const float*)d_in[1];
    const float* Wk = (const float*)d_in[2];
    const float* Wv = (const float*)d_in[3];
    const float* Wo = (const float*)d_in[4];
    float* out = (float*)d_out;

    float *qk, *v;
    cudaGetSymbolAddress((void**)&qk, g_qk);
    cudaGetSymbolAddress((void**)&v,  g_v);
    __nv_bfloat16 *hsH, *hsL, *wqkH, *wqkL, *wvH, *wvL, *woH, *woL, *yH, *yL;
    cudaGetSymbolAddress((void**)&hsH,  g_hsH);  cudaGetSymbolAddress((void**)&hsL,  g_hsL);
    cudaGetSymbolAddress((void**)&wqkH, g_wqkH); cudaGetSymbolAddress((void**)&wqkL, g_wqkL);
    cudaGetSymbolAddress((void**)&wvH,  g_wvH);  cudaGetSymbolAddress((void**)&wvL,  g_wvL);
    cudaGetSymbolAddress((void**)&woH,  g_woH);  cudaGetSymbolAddress((void**)&woL,  g_woL);
    cudaGetSymbolAddress((void**)&yH,   g_yH);   cudaGetSymbolAddress((void**)&yL,   g_yL);

    cudaFuncSetAttribute(chunk_kv_kernel, cudaFuncAttributeMaxDynamicSharedMemorySize, SMEM_A2);
    cudaFuncSetAttribute(attn_kernel,     cudaFuncAttributeMaxDynamicSharedMemorySize, SMEM_C2);
    cudaFuncSetAttribute(gemm_hmma,       cudaFuncAttributeMaxDynamicSharedMemorySize, SMEM_G);

    dim3 thr(256);
    conv_all<<<592, thr>>>(hs, Wq, Wk, Wv, Wo);

    gemm_hmma<<<dim3(NQK/128, MROWS/128), thr, SMEM_G>>>(hsH, hsL, wqkH, wqkL, qk, NQK);
    gemm_hmma<<<dim3(HID/128, MROWS/128), thr, SMEM_G>>>(hsH, hsL, wvH, wvL, v, HID);

    chunk_kv_kernel<<<BH*NC, thr, SMEM_A2>>>();
    scan_kernel<<<dim3(BH, 18), thr>>>();
    attn_kernel<<<BH*NC, thr, SMEM_C2>>>();

    gemm_hmma<<<dim3(HID/128, MROWS/128), thr, SMEM_G>>>(yH, yL, woH, woL, out, HID);
}

// round 14
// speedup vs baseline: 2.7918x; 1.1618x over previous
#include <cuda_runtime.h>
#include <cuda_bf16.h>
#include <cstdint>
#include <math.h>

// Problem constants
#define B_    2
#define T_    2048
#define HID   1536
#define NH    12
#define DK    16
#define DV    128
#define DF    273          // 1 + 16 + 256 taylor features
#define CH    128          // chunk length
#define NC    (T_/CH)      // 16 chunks
#define BH    (B_*NH)      // 24
#define MROWS (B_*T_)      // 4096
#define NQK   384          // q|k combined output cols (192+192)
#define GK    1536

#define INV4R2 0.17677669529663687f   // 1/(4*sqrt(2))

// ---------------- scratch (static device allocations; no cudaMalloc) ----------------
__device__ float g_qk[MROWS*NQK];        // [b*t][ q(0..191) | k(192..383) ]
__device__ float g_KV[(size_t)BH*NC*DF*DV];          // per-chunk KV sums (fp32)
__device__ float g_K1[(size_t)BH*NC*DF];
__device__ __nv_bfloat16 g_KVbH[(size_t)BH*NC*DF*DV]; // exclusive states, split bf16
__device__ __nv_bfloat16 g_KVbL[(size_t)BH*NC*DF*DV];

// bf16 split buffers
__device__ __nv_bfloat16 g_hsH[MROWS*HID], g_hsL[MROWS*HID];
__device__ __nv_bfloat16 g_wqkH[NQK*HID],  g_wqkL[NQK*HID];
__device__ __nv_bfloat16 g_wvH[HID*HID],   g_wvL[HID*HID];
__device__ __nv_bfloat16 g_woH[HID*HID],   g_woL[HID*HID];
__device__ __nv_bfloat16 g_vH[MROWS*HID],  g_vL[MROWS*HID];   // v projection, split
__device__ __nv_bfloat16 g_yH[MROWS*HID],  g_yL[MROWS*HID];

// ---------------- portable PTX helpers (valid on compute_103 base target) ----------------
__device__ __forceinline__ uint32_t smem_to_u32(const void* p) {
    uint32_t a;
    asm("{ .reg .u64 t; cvta.to.shared.u64 t, %1; cvt.u32.u64 %0, t; }" : "=r"(a) : "l"(p));
    return a;
}
#define CP_ASYNC16(dst, src) \
    asm volatile("cp.async.cg.shared.global [%0], [%1], 16;" :: "r"(dst), "l"(src) : "memory")
#define CP_COMMIT() asm volatile("cp.async.commit_group;" ::: "memory")
#define CP_WAIT1()  asm volatile("cp.async.wait_group 1;" ::: "memory")
#define CP_WAIT0()  asm volatile("cp.async.wait_group 0;" ::: "memory")

#define LDSM4(r0, r1, r2, r3, addr) \
    asm volatile("ldmatrix.sync.aligned.m8n8.x4.shared.b16 {%0,%1,%2,%3}, [%4];" \
        : "=r"(r0), "=r"(r1), "=r"(r2), "=r"(r3) : "r"(addr))
#define LDSM2(r0, r1, addr) \
    asm volatile("ldmatrix.sync.aligned.m8n8.x2.shared.b16 {%0,%1}, [%2];" \
        : "=r"(r0), "=r"(r1) : "r"(addr))
#define LDSM2T(r0, r1, addr) \
    asm volatile("ldmatrix.sync.aligned.m8n8.x2.trans.shared.b16 {%0,%1}, [%2];" \
        : "=r"(r0), "=r"(r1) : "r"(addr))

#define MMA16816(c, a, b) \
    asm volatile("mma.sync.aligned.m16n8k16.row.col.f32.bf16.bf16.f32 " \
        "{%0,%1,%2,%3}, {%4,%5,%6,%7}, {%8,%9}, {%0,%1,%2,%3};" \
        : "+f"((c)[0]), "+f"((c)[1]), "+f"((c)[2]), "+f"((c)[3]) \
        : "r"((a)[0]), "r"((a)[1]), "r"((a)[2]), "r"((a)[3]), "r"((b)[0]), "r"((b)[1]))

__device__ __forceinline__ void split2(float x, __nv_bfloat16& h, __nv_bfloat16& l) {
    h = __float2bfloat16(x);
    l = __float2bfloat16(x - __bfloat162float(h));
}

// feature f -> (ia, ib, scale) with virtual index 16 == constant 1
__device__ __forceinline__ void fdecomp(int f, int& ia, int& ib, float& sc) {
    if (f == 0)      { ia = 16; ib = 16; sc = 1.f; }
    else if (f < 17) { ia = f - 1; ib = 16; sc = 0.5f; }
    else { int p = f - 17; ia = p >> 4; ib = p & 15; sc = INV4R2; }
}

// ---------------- fused split-convert: all inputs -> (bf16 hi, bf16 lo) ----------------
#define N_HS  (MROWS*HID)
#define N_W1  (192*HID)
#define N_WV  (HID*HID)
__global__ __launch_bounds__(256) void conv_all(const float* __restrict__ hs,
                                                const float* __restrict__ Wq,
                                                const float* __restrict__ Wk,
                                                const float* __restrict__ Wv,
                                                const float* __restrict__ Wo) {
    const int total = N_HS + 2*N_W1 + 2*N_WV;
    for (int i = blockIdx.x*256 + threadIdx.x; i < total; i += gridDim.x*256) {
        float x; __nv_bfloat16 *ph, *pl; int off;
        int j = i;
        if (j < N_HS) { x = hs[j]; ph = g_hsH; pl = g_hsL; off = j; }
        else {
            j -= N_HS;
            if (j < N_W1) { x = Wq[j]; ph = g_wqkH; pl = g_wqkL; off = j; }
            else {
                j -= N_W1;
                if (j < N_W1) { x = Wk[j]; ph = g_wqkH; pl = g_wqkL; off = j + N_W1; }
                else {
                    j -= N_W1;
                    if (j < N_WV) { x = Wv[j]; ph = g_wvH; pl = g_wvL; off = j; }
                    else { j -= N_WV; x = Wo[j]; ph = g_woH; pl = g_woL; off = j; }
                }
            }
        }
        __nv_bfloat16 h, l; split2(x, h, l);
        ph[off] = h; pl[off] = l;
    }
}

// ---------------- HMMA split-bf16 GEMM: C[M,N] = A[M,K]@B[N,K]^T ----------------
// OUT=0: fp32 C.  OUT=1: split bf16 (CH, CL).
#define TSTRIDE 40
#define TILE_SB (128*TSTRIDE*2)
#define STAGE_SB (4*TILE_SB)
#define SMEM_G  (2*STAGE_SB)           // 81920 B
#define NSTAGE  (GK/32)                // 48

template<int OUT>
__global__ __launch_bounds__(256, 1) void gemm_hmma(const __nv_bfloat16* __restrict__ Ah,
                                                    const __nv_bfloat16* __restrict__ Al,
                                                    const __nv_bfloat16* __restrict__ Bh,
                                                    const __nv_bfloat16* __restrict__ Bl,
                                                    float* __restrict__ C,
                                                    __nv_bfloat16* __restrict__ CHp,
                                                    __nv_bfloat16* __restrict__ CLp,
                                                    int N) {
    extern __shared__ char smem[];
    const uint32_t sbase = smem_to_u32(smem);
    const int tid = threadIdx.x, wid = tid >> 5, lane = tid & 31;
    const int wm = wid & 1, wn = wid >> 1;
    const int bm = blockIdx.y * 128, bn = blockIdx.x * 128;

    const __nv_bfloat16* srcs[4] = {
        Ah + (size_t)bm * GK, Al + (size_t)bm * GK,
        Bh + (size_t)bn * GK, Bl + (size_t)bn * GK };

    auto stage_load = [&](int buf, int k0) {
        const uint32_t so = sbase + buf * STAGE_SB;
#pragma unroll
        for (int j = 0; j < 4; j++) {
            const __nv_bfloat16* src = srcs[j] + k0;
#pragma unroll
            for (int r = 0; r < 2; r++) {
                int c = tid + r * 256;
                int row = c >> 2, seg = c & 3;
                uint32_t d = so + (uint32_t)j * TILE_SB + (row * TSTRIDE + seg * 8) * 2;
                CP_ASYNC16(d, src + (size_t)row * GK + seg * 8);
            }
        }
        CP_COMMIT();
    };

    float acc[4][4][4];
#pragma unroll
    for (int i = 0; i < 4; i++)
#pragma unroll
        for (int j = 0; j < 4; j++)
#pragma unroll
            for (int r = 0; r < 4; r++) acc[i][j][r] = 0.f;

    stage_load(0, 0);
    stage_load(1, 32);

    const int arow = (lane & 7) + ((lane >> 3) & 1) * 8;
    const int acol8 = ((lane >> 4) & 1) * 8;
    const int brow = lane & 7;
    const int bcol8 = ((lane >> 3) & 1) * 8;

    for (int s = 0; s < NSTAGE; s++) {
        const int buf = s & 1;
        CP_WAIT1();
        __syncthreads();
        const uint32_t so = sbase + buf * STAGE_SB;
        const uint32_t aH = so, aL = so + TILE_SB, bH = so + 2*TILE_SB, bL = so + 3*TILE_SB;
#pragma unroll
        for (int kk = 0; kk < 2; kk++) {
            uint32_t ah[16], al[16], bh[8], bl[8];
            const int akc = kk * 16 + acol8;
            const int bkc = kk * 16 + bcol8;
#pragma unroll
            for (int mb = 0; mb < 4; mb++) {
                const uint32_t off = ((wm*64 + mb*16 + arow) * TSTRIDE + akc) * 2;
                LDSM4(ah[4*mb], ah[4*mb+1], ah[4*mb+2], ah[4*mb+3], aH + off);
                LDSM4(al[4*mb], al[4*mb+1], al[4*mb+2], al[4*mb+3], aL + off);
            }
#pragma unroll
            for (int nb = 0; nb < 4; nb++) {
                const uint32_t off = ((wn*32 + nb*8 + brow) * TSTRIDE + bkc) * 2;
                LDSM2(bh[2*nb], bh[2*nb+1], bH + off);
                LDSM2(bl[2*nb], bl[2*nb+1], bL + off);
            }
#pragma unroll
            for (int mb = 0; mb < 4; mb++)
#pragma unroll
                for (int nb = 0; nb < 4; nb++) {
                    MMA16816(acc[mb][nb], &ah[4*mb], &bh[2*nb]);
                    MMA16816(acc[mb][nb], &ah[4*mb], &bl[2*nb]);
                    MMA16816(acc[mb][nb], &al[4*mb], &bh[2*nb]);
                }
        }
        __syncthreads();
        if (s + 2 < NSTAGE) stage_load(buf, (s + 2) * 32);
    }
    CP_WAIT0();

    const int mrow = bm + wm*64 + (lane >> 2);
    const int ncol = bn + wn*32 + 2*(lane & 3);
#pragma unroll
    for (int mb = 0; mb < 4; mb++)
#pragma unroll
        for (int nb = 0; nb < 4; nb++) {
#pragma unroll
            for (int half = 0; half < 2; half++) {
                size_t off = (size_t)(mrow + mb*16 + half*8) * N + ncol + nb*8;
                float v0 = acc[mb][nb][2*half], v1 = acc[mb][nb][2*half+1];
                if (OUT == 0) {
                    *(float2*)&C[off] = make_float2(v0, v1);
                } else {
                    __nv_bfloat16 h0, l0, h1, l1;
                    split2(v0, h0, l0); split2(v1, h1, l1);
                    __nv_bfloat162 hv; hv.x = h0; hv.y = h1;
                    __nv_bfloat162 lv; lv.x = l0; lv.y = l1;
                    *(__nv_bfloat162*)&CHp[off] = hv;
                    *(__nv_bfloat162*)&CLp[off] = lv;
                }
            }
        }
}

// ---------------- Phase A: per-chunk KV[f][e] via HMMA ----------------
// KV[f][e] = sum_t kf[f][t]*v[t][e].  A = kf [f][t]; B = v [t][e] via ldmatrix.trans.
// smem: ks2 [128][17] fp32 | vtH/vtL [128][136] bf16 ([t][e]) | kfH/kfL [48][136] bf16
#define CKV_VST 136
#define CKV_FT  48
#define SMEM_A2 (128*17*4 + 2*(128*CKV_VST*2) + 2*(CKV_FT*CKV_VST*2))   // 104448 B

__global__ __launch_bounds__(256, 2) void chunk_kv_kernel() {
    extern __shared__ char smraw[];
    float* ks2 = (float*)smraw;                                  // [128][17]
    __nv_bfloat16* vtH = (__nv_bfloat16*)(smraw + 128*17*4);     // [128][136] [t][e]
    __nv_bfloat16* vtL = vtH + 128*CKV_VST;
    __nv_bfloat16* kfH = vtL + 128*CKV_VST;                      // [48][136]  [f][t]
    __nv_bfloat16* kfL = kfH + CKV_FT*CKV_VST;
    const uint32_t u_vtH = smem_to_u32(vtH), u_vtL = smem_to_u32(vtL);
    const uint32_t u_kfH = smem_to_u32(kfH), u_kfL = smem_to_u32(kfL);

    const int bid = blockIdx.x;
    const int bh = bid / NC, c = bid % NC;
    const int b = bh / NH, h = bh % NH;
    const int tid = threadIdx.x, wid = tid >> 5, lane = tid & 31;
    const size_t rowbase = (size_t)(b*T_ + c*CH);

    // stage v tiles [t][e] via cp.async from split-bf16 g_vH/g_vL (no conversion)
    for (int idx = tid; idx < 4096; idx += 256) {
        int bufs = idx >> 11;            // 0: hi, 1: lo
        int rem = idx & 2047;
        int row = rem >> 4, seg = rem & 15;
        const __nv_bfloat16* src = (bufs == 0 ? g_vH : g_vL)
            + (rowbase + row)*HID + h*DV + seg*8;
        uint32_t dst = (bufs == 0 ? u_vtH : u_vtL) + (uint32_t)(row*CKV_VST + seg*8)*2;
        CP_ASYNC16(dst, src);
    }
    CP_COMMIT();

    // load k (+ones) while cp.async in flight
    for (int idx = tid; idx < 128*16; idx += 256) {
        int t = idx >> 4, i = idx & 15;
        ks2[t*17 + i] = g_qk[(rowbase + t)*NQK + 192 + h*DK + i];
    }
    for (int idx = tid; idx < 128; idx += 256) ks2[idx*17 + 16] = 1.f;
    CP_WAIT0();
    __syncthreads();

    const int arow = (lane & 7) + ((lane >> 3) & 1) * 8;
    const int acol8 = ((lane >> 4) & 1) * 8;

    for (int fsub = 0; fsub < 6; fsub++) {
        // stage kf tile [48][128] split bf16
        for (int idx = tid; idx < CKV_FT*128; idx += 256) {
            int fl = idx >> 7, t = idx & 127;
            int f = fsub*CKV_FT + fl;
            float val = 0.f;
            if (f < DF) {
                int ia, ib; float sc; fdecomp(f, ia, ib, sc);
                val = ks2[t*17 + ia] * ks2[t*17 + ib] * sc;
            }
            __nv_bfloat16 hh, ll; split2(val, hh, ll);
            kfH[fl*CKV_VST + t] = hh; kfL[fl*CKV_VST + t] = ll;
        }
        __syncthreads();

        float acc[3][2][4];
#pragma unroll
        for (int i = 0; i < 3; i++)
#pragma unroll
            for (int j = 0; j < 2; j++)
#pragma unroll
                for (int r = 0; r < 4; r++) acc[i][j][r] = 0.f;

#pragma unroll
        for (int kc = 0; kc < 8; kc++) {
            const int t0 = kc * 16;
            uint32_t ah[12], al[12], bhr[4], blr[4];
#pragma unroll
            for (int mb = 0; mb < 3; mb++) {
                const uint32_t off = ((mb*16 + arow) * CKV_VST + t0 + acol8) * 2;
                LDSM4(ah[4*mb], ah[4*mb+1], ah[4*mb+2], ah[4*mb+3], u_kfH + off);
                LDSM4(al[4*mb], al[4*mb+1], al[4*mb+2], al[4*mb+3], u_kfL + off);
            }
#pragma unroll
            for (int nb = 0; nb < 2; nb++) {
                // trans load: [t][e] rows t0+lane%16, col wid*16 + nb*8
                const uint32_t off = ((t0 + (lane & 15)) * CKV_VST + wid*16 + nb*8) * 2;
                LDSM2T(bhr[2*nb], bhr[2*nb+1], u_vtH + off);
                LDSM2T(blr[2*nb], blr[2*nb+1], u_vtL + off);
            }
#pragma unroll
            for (int mb = 0; mb < 3; mb++)
#pragma unroll
                for (int nb = 0; nb < 2; nb++) {
                    MMA16816(acc[mb][nb], &ah[4*mb], &bhr[2*nb]);
                    MMA16816(acc[mb][nb], &ah[4*mb], &blr[2*nb]);
                    MMA16816(acc[mb][nb], &al[4*mb], &bhr[2*nb]);
                }
        }

        // epilogue
        const int e0 = wid*16 + 2*(lane & 3);
#pragma unroll
        for (int mb = 0; mb < 3; mb++) {
            int f0 = fsub*CKV_FT + mb*16 + (lane >> 2);
#pragma unroll
            for (int nb = 0; nb < 2; nb++) {
                if (f0 < DF)
                    *(float2*)&g_KV[((size_t)bid*DF + f0)*DV + e0 + nb*8] =
                        make_float2(acc[mb][nb][0], acc[mb][nb][1]);
                if (f0 + 8 < DF)
                    *(float2*)&g_KV[((size_t)bid*DF + f0 + 8)*DV + e0 + nb*8] =
                        make_float2(acc[mb][nb][2], acc[mb][nb][3]);
            }
        }
        __syncthreads();
    }

    // K1[f] = sum_t kf[f][t]  (FFMA, tiny)
    for (int f = tid; f < DF; f += 256) {
        int ia, ib; float sc; fdecomp(f, ia, ib, sc);
        float s = 0.f;
#pragma unroll 4
        for (int t = 0; t < 128; t++) s += ks2[t*17+ia]*ks2[t*17+ib];
        g_K1[(size_t)bid*DF + f] = s*sc;
    }
}

// ---------------- Phase B: exclusive scan; KV states written as split bf16 ----------------
__global__ __launch_bounds__(256) void scan_kernel() {
    const int bh = blockIdx.x;
    const int part = blockIdx.y;             // 0..17
    const int stride = 18*256;
    size_t baseKV = (size_t)bh*NC*DF*DV;
    for (int idx = part*256 + threadIdx.x; idx < DF*DV; idx += stride) {
        float prev = 0.f;
        size_t p = baseKV + idx;
#pragma unroll
        for (int cc = 0; cc < NC; cc++) {
            float tmp = g_KV[p];
            __nv_bfloat16 hh, ll; split2(prev, hh, ll);
            g_KVbH[p] = hh; g_KVbL[p] = ll;
            prev += tmp;
            p += (size_t)DF*DV;
        }
    }
    if (part == 0) {
        size_t baseK = (size_t)bh*NC*DF;
        for (int idx = threadIdx.x; idx < DF; idx += 256) {
            float prev = 0.f; size_t p = baseK + idx;
#pragma unroll
            for (int cc = 0; cc < NC; cc++) {
                float tmp = g_K1[p]; g_K1[p] = prev; prev += tmp; p += DF;
            }
        }
    }
}

// ---------------- Phase C: fused inter + intra attention via HMMA ----------------
// smem fp32: qT2 [17][128], kT [16][128], Ss [128][132], stK [288], dsh [128]
// smem bf16: aH/aL [128][24] ([t][k]); bH/bL [16][136] ([k][e], trans-loaded)
#define ATT_AST 24
#define ATT_BST 136
#define ATT_F32 (17*128 + 16*128 + 128*132 + 288 + 128)
#define SMEM_C2 (ATT_F32*4 + 2*(128*ATT_AST*2) + 2*(16*ATT_BST*2))   // 107136 B

__global__ __launch_bounds__(256, 2) void attn_kernel() {
    extern __shared__ char smraw[];
    float* qT2 = (float*)smraw;          // [17][128]
    float* kT  = qT2 + 17*128;           // [16][128]
    float* Ss  = kT  + 16*128;           // [128][132]
    float* stK = Ss  + 128*132;          // [288]
    float* dsh = stK + 288;              // [128]
    __nv_bfloat16* aHp = (__nv_bfloat16*)(smraw + ATT_F32*4);
    __nv_bfloat16* aLp = aHp + 128*ATT_AST;
    __nv_bfloat16* bHp = aLp + 128*ATT_AST;   // [16][136]
    __nv_bfloat16* bLp = bHp + 16*ATT_BST;
    const uint32_t u_aH = smem_to_u32(aHp), u_aL = smem_to_u32(aLp);
    const uint32_t u_bH = smem_to_u32(bHp), u_bL = smem_to_u32(bLp);

    const int bid = blockIdx.x;
    const int bh = bid / NC, c = bid % NC;
    const int b = bh / NH, h = bh % NH;
    const int tid = threadIdx.x, wid = tid >> 5, lane = tid & 31;
    const int wm = wid & 1, wn = wid >> 1;
    const int tx = tid & 15, ty = tid >> 4;
    const size_t rowbase = (size_t)(b*T_ + c*CH);

    for (int idx = tid; idx < 128*16; idx += 256) {
        int t = idx >> 4, i = idx & 15;
        qT2[i*128 + t] = g_qk[(rowbase + t)*NQK + h*DK + i];
        kT [i*128 + t] = g_qk[(rowbase + t)*NQK + 192 + h*DK + i];
    }
    for (int idx = tid; idx < 128; idx += 256) qT2[16*128 + idx] = 1.f;
    for (int f = tid; f < DF; f += 256) stK[f] = g_K1[(size_t)bid*DF + f];
    __syncthreads();

    // ---- S[t][s] = phi(q_t . k_s), causal; phi(x)=1+x/4+x^2/32 (fp32) ----
    {
        float sacc[8][8];
#pragma unroll
        for (int i = 0; i < 8; i++)
#pragma unroll
            for (int j = 0; j < 8; j++) sacc[i][j] = 0.f;
#pragma unroll
        for (int kk = 0; kk < 16; kk++) {
            float a[8], bb[8];
            *(float4*)(a)    = *(const float4*)&qT2[kk*128 + ty*8];
            *(float4*)(a+4)  = *(const float4*)&qT2[kk*128 + ty*8 + 4];
            *(float4*)(bb)   = *(const float4*)&kT [kk*128 + tx*8];
            *(float4*)(bb+4) = *(const float4*)&kT [kk*128 + tx*8 + 4];
#pragma unroll
            for (int i = 0; i < 8; i++)
#pragma unroll
                for (int j = 0; j < 8; j++) sacc[i][j] += a[i]*bb[j];
        }
#pragma unroll
        for (int i = 0; i < 8; i++) {
            int t = ty*8 + i;
#pragma unroll
            for (int j = 0; j < 8; j++) {
                int s = tx*8 + j;
                float d = sacc[i][j];
                Ss[t*132 + s] = (s <= t) ? (1.f + 0.25f*d + 0.03125f*d*d) : 0.f;
            }
        }
    }
    __syncthreads();

    // ---- denominators ----
    if (tid < 128) {
        const int t = tid;
        float qv[16];
#pragma unroll
        for (int i = 0; i < 16; i++) qv[i] = qT2[i*128 + t];
        float dacc = stK[0];
#pragma unroll
        for (int i = 0; i < 16; i++) dacc += qv[i]*0.5f*stK[1+i];
#pragma unroll
        for (int i = 0; i < 16; i++) {
            float qi = qv[i]*INV4R2;
#pragma unroll
            for (int j = 0; j < 16; j++)
                dacc += qi*qv[j]*stK[17 + i*16 + j];
        }
        float di = 0.f;
        for (int s = 0; s < 128; s++) di += Ss[t*132 + s];
        dsh[t] = dacc + di + 1e-12f;
    }

    const int arow = (lane & 7) + ((lane >> 3) & 1) * 8;
    const int acol8 = ((lane >> 4) & 1) * 8;

    float acc[4][4][4];
#pragma unroll
    for (int i = 0; i < 4; i++)
#pragma unroll
        for (int j = 0; j < 4; j++)
#pragma unroll
            for (int r = 0; r < 4; r++) acc[i][j][r] = 0.f;

    // ---- 26 k-chunks: 18 inter (qf @ state) + 8 intra (S @ v) ----
    for (int ch = 0; ch < 26; ch++) {
        __syncthreads();
        // B tile: [k=16][e=128] via cp.async (rows from bf16 gmem, no conversion)
        for (int idx = tid; idx < 512; idx += 256) {
            int bufs = idx >> 8;
            int rem = idx & 255;
            int r = rem >> 4, seg = rem & 15;
            uint32_t dst = (bufs == 0 ? u_bH : u_bL) + (uint32_t)(r*ATT_BST + seg*8)*2;
            if (ch < 18) {
                int f = ch*16 + r;
                if (f < DF) {
                    const __nv_bfloat16* src = (bufs == 0 ? g_KVbH : g_KVbL)
                        + ((size_t)bid*DF + f)*DV + seg*8;
                    CP_ASYNC16(dst, src);
                } else {
                    *(uint4*)((char*)smraw + (dst - smem_to_u32(smraw))) = make_uint4(0,0,0,0);
                }
            } else {
                int s0 = (ch - 18)*16;
                const __nv_bfloat16* src = (bufs == 0 ? g_vH : g_vL)
                    + (rowbase + s0 + r)*HID + h*DV + seg*8;
                CP_ASYNC16(dst, src);
            }
        }
        CP_COMMIT();

        // A tile: [t][k=16] computed + split
        if (ch < 18) {
            const int f0 = ch * 16;
            for (int idx = tid; idx < 2048; idx += 256) {
                int t = idx >> 4, kk = idx & 15;
                int f = f0 + kk;
                float val = 0.f;
                if (f < DF) {
                    int ia, ib; float sc; fdecomp(f, ia, ib, sc);
                    val = qT2[ia*128 + t] * qT2[ib*128 + t] * sc;
                }
                __nv_bfloat16 hh, ll; split2(val, hh, ll);
                aHp[t*ATT_AST + kk] = hh; aLp[t*ATT_AST + kk] = ll;
            }
        } else {
            const int s0 = (ch - 18) * 16;
            for (int idx = tid; idx < 2048; idx += 256) {
                int t = idx >> 4, kk = idx & 15;
                float val = Ss[t*132 + s0 + kk];
                __nv_bfloat16 hh, ll; split2(val, hh, ll);
                aHp[t*ATT_AST + kk] = hh; aLp[t*ATT_AST + kk] = ll;
            }
        }
        CP_WAIT0();
        __syncthreads();

        uint32_t ah[16], al[16], bhr[8], blr[8];
#pragma unroll
        for (int mb = 0; mb < 4; mb++) {
            const uint32_t off = ((wm*64 + mb*16 + arow) * ATT_AST + acol8) * 2;
            LDSM4(ah[4*mb], ah[4*mb+1], ah[4*mb+2], ah[4*mb+3], u_aH + off);
            LDSM4(al[4*mb], al[4*mb+1], al[4*mb+2], al[4*mb+3], u_aL + off);
        }
#pragma unroll
        for (int nb = 0; nb < 4; nb++) {
            // trans load: rows k = lane%16, col wn*32 + nb*8
            const uint32_t off = ((lane & 15) * ATT_BST + wn*32 + nb*8) * 2;
            LDSM2T(bhr[2*nb], bhr[2*nb+1], u_bH + off);
            LDSM2T(blr[2*nb], blr[2*nb+1], u_bL + off);
        }
#pragma unroll
        for (int mb = 0; mb < 4; mb++)
#pragma unroll
            for (int nb = 0; nb < 4; nb++) {
                MMA16816(acc[mb][nb], &ah[4*mb], &bhr[2*nb]);
                MMA16816(acc[mb][nb], &ah[4*mb], &blr[2*nb]);
                MMA16816(acc[mb][nb], &al[4*mb], &bhr[2*nb]);
            }
    }
    __syncthreads();

    // ---- epilogue: divide by den, write split bf16 y ----
    const int e0 = wn*32 + 2*(lane & 3);
#pragma unroll
    for (int mb = 0; mb < 4; mb++) {
        int t0 = wm*64 + mb*16 + (lane >> 2);
#pragma unroll
        for (int half = 0; half < 2; half++) {
            int t = t0 + half*8;
            float r = 1.f / dsh[t];
            size_t row = (rowbase + t)*HID + h*DV;
#pragma unroll
            for (int nb = 0; nb < 4; nb++) {
                float y0 = acc[mb][nb][2*half]   * r;
                float y1 = acc[mb][nb][2*half+1] * r;
                __nv_bfloat16 h0, l0, h1, l1;
                split2(y0, h0, l0); split2(y1, h1, l1);
                __nv_bfloat162 hv; hv.x = h0; hv.y = h1;
                __nv_bfloat162 lv; lv.x = l0; lv.y = l1;
                *(__nv_bfloat162*)&g_yH[row + e0 + nb*8] = hv;
                *(__nv_bfloat162*)&g_yL[row + e0 + nb*8] = lv;
            }
        }
    }
}

// ---------------- launch ----------------
extern "C" void kernel_launch(void* const* d_in, const int* in_sizes, int n_in,
                              void* d_out, int out_size) {
    const float* hs = (const float*)d_in[0];
    const float* Wq = (const float*)d_in[1];
    const float* Wk = (const float*)d_in[2];
    const float* Wv = (const float*)d_in[3];
    const float* Wo = (const float*)d_in[4];
    float* out = (float*)d_out;

    float *qk;
    cudaGetSymbolAddress((void**)&qk, g_qk);
    __nv_bfloat16 *hsH, *hsL, *wqkH, *wqkL, *wvH, *wvL, *woH, *woL, *yH, *yL, *vH, *vL;
    cudaGetSymbolAddress((void**)&hsH,  g_hsH);  cudaGetSymbolAddress((void**)&hsL,  g_hsL);
    cudaGetSymbolAddress((void**)&wqkH, g_wqkH); cudaGetSymbolAddress((void**)&wqkL, g_wqkL);
    cudaGetSymbolAddress((void**)&wvH,  g_wvH);  cudaGetSymbolAddress((void**)&wvL,  g_wvL);
    cudaGetSymbolAddress((void**)&woH,  g_woH);  cudaGetSymbolAddress((void**)&woL,  g_woL);
    cudaGetSymbolAddress((void**)&yH,   g_yH);   cudaGetSymbolAddress((void**)&yL,   g_yL);
    cudaGetSymbolAddress((void**)&vH,   g_vH);   cudaGetSymbolAddress((void**)&vL,   g_vL);

    cudaFuncSetAttribute(chunk_kv_kernel, cudaFuncAttributeMaxDynamicSharedMemorySize, SMEM_A2);
    cudaFuncSetAttribute(attn_kernel,     cudaFuncAttributeMaxDynamicSharedMemorySize, SMEM_C2);
    cudaFuncSetAttribute(gemm_hmma<0>,    cudaFuncAttributeMaxDynamicSharedMemorySize, SMEM_G);
    cudaFuncSetAttribute(gemm_hmma<1>,    cudaFuncAttributeMaxDynamicSharedMemorySize, SMEM_G);

    dim3 thr(256);
    conv_all<<<592, thr>>>(hs, Wq, Wk, Wv, Wo);

    // projections
    gemm_hmma<0><<<dim3(NQK/128, MROWS/128), thr, SMEM_G>>>(hsH, hsL, wqkH, wqkL, qk, nullptr, nullptr, NQK);
    gemm_hmma<1><<<dim3(HID/128, MROWS/128), thr, SMEM_G>>>(hsH, hsL, wvH, wvL, nullptr, vH, vL, HID);

    chunk_kv_kernel<<<BH*NC, thr, SMEM_A2>>>();
    scan_kernel<<<dim3(BH, 18), thr>>>();
    attn_kernel<<<BH*NC, thr, SMEM_C2>>>();

    gemm_hmma<0><<<dim3(HID/128, MROWS/128), thr, SMEM_G>>>(yH, yL, woH, woL, out, nullptr, nullptr, HID);
}

// round 16
// speedup vs baseline: 2.9839x; 1.0688x over previous
#include <cuda_runtime.h>
#include <cuda_bf16.h>
#include <cstdint>
#include <math.h>

// Problem constants
#define B_    2
#define T_    2048
#define HID   1536
#define NH    12
#define DK    16
#define DV    128
#define DF    273          // 1 + 16 + 256 taylor features
#define CH    128          // chunk length
#define NC    (T_/CH)      // 16 chunks
#define BH    (B_*NH)      // 24
#define MROWS (B_*T_)      // 4096
#define NQK   384          // q|k combined output cols (192+192)
#define GK    1536

#define INV4R2 0.17677669529663687f   // 1/(4*sqrt(2))

// ---------------- scratch (static device allocations; no cudaMalloc) ----------------
__device__ float g_qk[MROWS*NQK];        // [b*t][ q(0..191) | k(192..383) ]
__device__ float g_KV[(size_t)BH*NC*DF*DV];          // per-chunk KV sums (fp32)
__device__ float g_K1[(size_t)BH*NC*DF];
__device__ __nv_bfloat16 g_KVbH[(size_t)BH*NC*DF*DV]; // exclusive states, split bf16
__device__ __nv_bfloat16 g_KVbL[(size_t)BH*NC*DF*DV];

// bf16 split buffers
__device__ __nv_bfloat16 g_hsH[MROWS*HID], g_hsL[MROWS*HID];
__device__ __nv_bfloat16 g_wqkH[NQK*HID],  g_wqkL[NQK*HID];
__device__ __nv_bfloat16 g_wvH[HID*HID],   g_wvL[HID*HID];
__device__ __nv_bfloat16 g_woH[HID*HID],   g_woL[HID*HID];
__device__ __nv_bfloat16 g_vH[MROWS*HID],  g_vL[MROWS*HID];   // v projection, split
__device__ __nv_bfloat16 g_yH[MROWS*HID],  g_yL[MROWS*HID];

// ---------------- portable PTX helpers (valid on compute_103 base target) ----------------
__device__ __forceinline__ uint32_t smem_to_u32(const void* p) {
    uint32_t a;
    asm("{ .reg .u64 t; cvta.to.shared.u64 t, %1; cvt.u32.u64 %0, t; }" : "=r"(a) : "l"(p));
    return a;
}
#define CP_ASYNC16(dst, src) \
    asm volatile("cp.async.cg.shared.global [%0], [%1], 16;" :: "r"(dst), "l"(src) : "memory")
#define CP_COMMIT() asm volatile("cp.async.commit_group;" ::: "memory")
#define CP_WAIT1()  asm volatile("cp.async.wait_group 1;" ::: "memory")
#define CP_WAIT0()  asm volatile("cp.async.wait_group 0;" ::: "memory")

#define LDSM4(r0, r1, r2, r3, addr) \
    asm volatile("ldmatrix.sync.aligned.m8n8.x4.shared.b16 {%0,%1,%2,%3}, [%4];" \
        : "=r"(r0), "=r"(r1), "=r"(r2), "=r"(r3) : "r"(addr))
#define LDSM2(r0, r1, addr) \
    asm volatile("ldmatrix.sync.aligned.m8n8.x2.shared.b16 {%0,%1}, [%2];" \
        : "=r"(r0), "=r"(r1) : "r"(addr))
#define LDSM2T(r0, r1, addr) \
    asm volatile("ldmatrix.sync.aligned.m8n8.x2.trans.shared.b16 {%0,%1}, [%2];" \
        : "=r"(r0), "=r"(r1) : "r"(addr))

#define MMA16816(c, a, b) \
    asm volatile("mma.sync.aligned.m16n8k16.row.col.f32.bf16.bf16.f32 " \
        "{%0,%1,%2,%3}, {%4,%5,%6,%7}, {%8,%9}, {%0,%1,%2,%3};" \
        : "+f"((c)[0]), "+f"((c)[1]), "+f"((c)[2]), "+f"((c)[3]) \
        : "r"((a)[0]), "r"((a)[1]), "r"((a)[2]), "r"((a)[3]), "r"((b)[0]), "r"((b)[1]))

__device__ __forceinline__ void split2(float x, __nv_bfloat16& h, __nv_bfloat16& l) {
    h = __float2bfloat16(x);
    l = __float2bfloat16(x - __bfloat162float(h));
}

// feature f -> (ia, ib, scale) with virtual index 16 == constant 1
__device__ __forceinline__ void fdecomp(int f, int& ia, int& ib, float& sc) {
    if (f == 0)      { ia = 16; ib = 16; sc = 1.f; }
    else if (f < 17) { ia = f - 1; ib = 16; sc = 0.5f; }
    else { int p = f - 17; ia = p >> 4; ib = p & 15; sc = INV4R2; }
}

// ---------------- fused split-convert: all inputs -> (bf16 hi, bf16 lo) ----------------
#define N_HS  (MROWS*HID)
#define N_W1  (192*HID)
#define N_WV  (HID*HID)
__global__ __launch_bounds__(256) void conv_all(const float* __restrict__ hs,
                                                const float* __restrict__ Wq,
                                                const float* __restrict__ Wk,
                                                const float* __restrict__ Wv,
                                                const float* __restrict__ Wo) {
    const int total = N_HS + 2*N_W1 + 2*N_WV;
    for (int i = blockIdx.x*256 + threadIdx.x; i < total; i += gridDim.x*256) {
        float x; __nv_bfloat16 *ph, *pl; int off;
        int j = i;
        if (j < N_HS) { x = hs[j]; ph = g_hsH; pl = g_hsL; off = j; }
        else {
            j -= N_HS;
            if (j < N_W1) { x = Wq[j]; ph = g_wqkH; pl = g_wqkL; off = j; }
            else {
                j -= N_W1;
                if (j < N_W1) { x = Wk[j]; ph = g_wqkH; pl = g_wqkL; off = j + N_W1; }
                else {
                    j -= N_W1;
                    if (j < N_WV) { x = Wv[j]; ph = g_wvH; pl = g_wvL; off = j; }
                    else { j -= N_WV; x = Wo[j]; ph = g_woH; pl = g_woL; off = j; }
                }
            }
        }
        __nv_bfloat16 h, l; split2(x, h, l);
        ph[off] = h; pl[off] = l;
    }
}

// ---------------- HMMA split-bf16 GEMM: C[M,N] = A[M,K]@B[N,K]^T ----------------
// OUT=0: fp32 C.  OUT=1: split bf16 (CH, CL).
#define TSTRIDE 40
#define TILE_SB (128*TSTRIDE*2)
#define STAGE_SB (4*TILE_SB)
#define SMEM_G  (2*STAGE_SB)           // 81920 B
#define NSTAGE  (GK/32)                // 48

template<int OUT>
__global__ __launch_bounds__(256, 2) void gemm_hmma(const __nv_bfloat16* __restrict__ Ah,
                                                    const __nv_bfloat16* __restrict__ Al,
                                                    const __nv_bfloat16* __restrict__ Bh,
                                                    const __nv_bfloat16* __restrict__ Bl,
                                                    float* __restrict__ C,
                                                    __nv_bfloat16* __restrict__ CHp,
                                                    __nv_bfloat16* __restrict__ CLp,
                                                    int N) {
    extern __shared__ char smem[];
    const uint32_t sbase = smem_to_u32(smem);
    const int tid = threadIdx.x, wid = tid >> 5, lane = tid & 31;
    const int wm = wid & 1, wn = wid >> 1;
    const int bm = blockIdx.y * 128, bn = blockIdx.x * 128;

    const __nv_bfloat16* srcs[4] = {
        Ah + (size_t)bm * GK, Al + (size_t)bm * GK,
        Bh + (size_t)bn * GK, Bl + (size_t)bn * GK };

    auto stage_load = [&](int buf, int k0) {
        const uint32_t so = sbase + buf * STAGE_SB;
#pragma unroll
        for (int j = 0; j < 4; j++) {
            const __nv_bfloat16* src = srcs[j] + k0;
#pragma unroll
            for (int r = 0; r < 2; r++) {
                int c = tid + r * 256;
                int row = c >> 2, seg = c & 3;
                uint32_t d = so + (uint32_t)j * TILE_SB + (row * TSTRIDE + seg * 8) * 2;
                CP_ASYNC16(d, src + (size_t)row * GK + seg * 8);
            }
        }
        CP_COMMIT();
    };

    float acc[4][4][4];
#pragma unroll
    for (int i = 0; i < 4; i++)
#pragma unroll
        for (int j = 0; j < 4; j++)
#pragma unroll
            for (int r = 0; r < 4; r++) acc[i][j][r] = 0.f;

    stage_load(0, 0);
    stage_load(1, 32);

    const int arow = (lane & 7) + ((lane >> 3) & 1) * 8;
    const int acol8 = ((lane >> 4) & 1) * 8;
    const int brow = lane & 7;
    const int bcol8 = ((lane >> 3) & 1) * 8;

    for (int s = 0; s < NSTAGE; s++) {
        const int buf = s & 1;
        CP_WAIT1();
        __syncthreads();
        const uint32_t so = sbase + buf * STAGE_SB;
        const uint32_t aH = so, aL = so + TILE_SB, bH = so + 2*TILE_SB, bL = so + 3*TILE_SB;
#pragma unroll
        for (int kk = 0; kk < 2; kk++) {
            uint32_t ah[16], al[16], bh[8], bl[8];
            const int akc = kk * 16 + acol8;
            const int bkc = kk * 16 + bcol8;
#pragma unroll
            for (int mb = 0; mb < 4; mb++) {
                const uint32_t off = ((wm*64 + mb*16 + arow) * TSTRIDE + akc) * 2;
                LDSM4(ah[4*mb], ah[4*mb+1], ah[4*mb+2], ah[4*mb+3], aH + off);
                LDSM4(al[4*mb], al[4*mb+1], al[4*mb+2], al[4*mb+3], aL + off);
            }
#pragma unroll
            for (int nb = 0; nb < 4; nb++) {
                const uint32_t off = ((wn*32 + nb*8 + brow) * TSTRIDE + bkc) * 2;
                LDSM2(bh[2*nb], bh[2*nb+1], bH + off);
                LDSM2(bl[2*nb], bl[2*nb+1], bL + off);
            }
#pragma unroll
            for (int mb = 0; mb < 4; mb++)
#pragma unroll
                for (int nb = 0; nb < 4; nb++) {
                    MMA16816(acc[mb][nb], &ah[4*mb], &bh[2*nb]);
                    MMA16816(acc[mb][nb], &ah[4*mb], &bl[2*nb]);
                    MMA16816(acc[mb][nb], &al[4*mb], &bh[2*nb]);
                }
        }
        __syncthreads();
        if (s + 2 < NSTAGE) stage_load(buf, (s + 2) * 32);
    }
    CP_WAIT0();

    const int mrow = bm + wm*64 + (lane >> 2);
    const int ncol = bn + wn*32 + 2*(lane & 3);
#pragma unroll
    for (int mb = 0; mb < 4; mb++)
#pragma unroll
        for (int nb = 0; nb < 4; nb++) {
#pragma unroll
            for (int half = 0; half < 2; half++) {
                size_t off = (size_t)(mrow + mb*16 + half*8) * N + ncol + nb*8;
                float v0 = acc[mb][nb][2*half], v1 = acc[mb][nb][2*half+1];
                if (OUT == 0) {
                    *(float2*)&C[off] = make_float2(v0, v1);
                } else {
                    __nv_bfloat16 h0, l0, h1, l1;
                    split2(v0, h0, l0); split2(v1, h1, l1);
                    __nv_bfloat162 hv; hv.x = h0; hv.y = h1;
                    __nv_bfloat162 lv; lv.x = l0; lv.y = l1;
                    *(__nv_bfloat162*)&CHp[off] = hv;
                    *(__nv_bfloat162*)&CLp[off] = lv;
                }
            }
        }
}

// ---------------- Phase A: per-chunk KV[f][e] via HMMA ----------------
// KV[f][e] = sum_t kf[f][t]*v[t][e].  A = kf [f][t]; B = v [t][e] via ldmatrix.trans.
// smem: ks2 [128][17] fp32 | vtH/vtL [128][136] bf16 ([t][e]) | kfH/kfL [48][136] bf16
#define CKV_VST 136
#define CKV_FT  48
#define SMEM_A2 (128*17*4 + 2*(128*CKV_VST*2) + 2*(CKV_FT*CKV_VST*2))   // 104448 B

__global__ __launch_bounds__(256, 2) void chunk_kv_kernel() {
    extern __shared__ char smraw[];
    float* ks2 = (float*)smraw;                                  // [128][17]
    __nv_bfloat16* vtH = (__nv_bfloat16*)(smraw + 128*17*4);     // [128][136] [t][e]
    __nv_bfloat16* vtL = vtH + 128*CKV_VST;
    __nv_bfloat16* kfH = vtL + 128*CKV_VST;                      // [48][136]  [f][t]
    __nv_bfloat16* kfL = kfH + CKV_FT*CKV_VST;
    const uint32_t u_vtH = smem_to_u32(vtH), u_vtL = smem_to_u32(vtL);
    const uint32_t u_kfH = smem_to_u32(kfH), u_kfL = smem_to_u32(kfL);

    const int bid = blockIdx.x;
    const int bh = bid / NC, c = bid % NC;
    const int b = bh / NH, h = bh % NH;
    const int tid = threadIdx.x, wid = tid >> 5, lane = tid & 31;
    const size_t rowbase = (size_t)(b*T_ + c*CH);

    // stage v tiles [t][e] via cp.async from split-bf16 g_vH/g_vL (no conversion)
    for (int idx = tid; idx < 4096; idx += 256) {
        int bufs = idx >> 11;            // 0: hi, 1: lo
        int rem = idx & 2047;
        int row = rem >> 4, seg = rem & 15;
        const __nv_bfloat16* src = (bufs == 0 ? g_vH : g_vL)
            + (rowbase + row)*HID + h*DV + seg*8;
        uint32_t dst = (bufs == 0 ? u_vtH : u_vtL) + (uint32_t)(row*CKV_VST + seg*8)*2;
        CP_ASYNC16(dst, src);
    }
    CP_COMMIT();

    // load k (+ones) while cp.async in flight
    for (int idx = tid; idx < 128*16; idx += 256) {
        int t = idx >> 4, i = idx & 15;
        ks2[t*17 + i] = g_qk[(rowbase + t)*NQK + 192 + h*DK + i];
    }
    for (int idx = tid; idx < 128; idx += 256) ks2[idx*17 + 16] = 1.f;
    CP_WAIT0();
    __syncthreads();

    const int arow = (lane & 7) + ((lane >> 3) & 1) * 8;
    const int acol8 = ((lane >> 4) & 1) * 8;

    for (int fsub = 0; fsub < 6; fsub++) {
        // stage kf tile [48][128] split bf16
        for (int idx = tid; idx < CKV_FT*128; idx += 256) {
            int fl = idx >> 7, t = idx & 127;
            int f = fsub*CKV_FT + fl;
            float val = 0.f;
            if (f < DF) {
                int ia, ib; float sc; fdecomp(f, ia, ib, sc);
                val = ks2[t*17 + ia] * ks2[t*17 + ib] * sc;
            }
            __nv_bfloat16 hh, ll; split2(val, hh, ll);
            kfH[fl*CKV_VST + t] = hh; kfL[fl*CKV_VST + t] = ll;
        }
        __syncthreads();

        float acc[3][2][4];
#pragma unroll
        for (int i = 0; i < 3; i++)
#pragma unroll
            for (int j = 0; j < 2; j++)
#pragma unroll
                for (int r = 0; r < 4; r++) acc[i][j][r] = 0.f;

#pragma unroll
        for (int kc = 0; kc < 8; kc++) {
            const int t0 = kc * 16;
            uint32_t ah[12], al[12], bhr[4], blr[4];
#pragma unroll
            for (int mb = 0; mb < 3; mb++) {
                const uint32_t off = ((mb*16 + arow) * CKV_VST + t0 + acol8) * 2;
                LDSM4(ah[4*mb], ah[4*mb+1], ah[4*mb+2], ah[4*mb+3], u_kfH + off);
                LDSM4(al[4*mb], al[4*mb+1], al[4*mb+2], al[4*mb+3], u_kfL + off);
            }
#pragma unroll
            for (int nb = 0; nb < 2; nb++) {
                // trans load: [t][e] rows t0+lane%16, col wid*16 + nb*8
                const uint32_t off = ((t0 + (lane & 15)) * CKV_VST + wid*16 + nb*8) * 2;
                LDSM2T(bhr[2*nb], bhr[2*nb+1], u_vtH + off);
                LDSM2T(blr[2*nb], blr[2*nb+1], u_vtL + off);
            }
#pragma unroll
            for (int mb = 0; mb < 3; mb++)
#pragma unroll
                for (int nb = 0; nb < 2; nb++) {
                    MMA16816(acc[mb][nb], &ah[4*mb], &bhr[2*nb]);
                    MMA16816(acc[mb][nb], &ah[4*mb], &blr[2*nb]);
                    MMA16816(acc[mb][nb], &al[4*mb], &bhr[2*nb]);
                }
        }

        // epilogue
        const int e0 = wid*16 + 2*(lane & 3);
#pragma unroll
        for (int mb = 0; mb < 3; mb++) {
            int f0 = fsub*CKV_FT + mb*16 + (lane >> 2);
#pragma unroll
            for (int nb = 0; nb < 2; nb++) {
                if (f0 < DF)
                    *(float2*)&g_KV[((size_t)bid*DF + f0)*DV + e0 + nb*8] =
                        make_float2(acc[mb][nb][0], acc[mb][nb][1]);
                if (f0 + 8 < DF)
                    *(float2*)&g_KV[((size_t)bid*DF + f0 + 8)*DV + e0 + nb*8] =
                        make_float2(acc[mb][nb][2], acc[mb][nb][3]);
            }
        }
        __syncthreads();
    }

    // K1[f] = sum_t kf[f][t]  (FFMA, tiny)
    for (int f = tid; f < DF; f += 256) {
        int ia, ib; float sc; fdecomp(f, ia, ib, sc);
        float s = 0.f;
#pragma unroll 4
        for (int t = 0; t < 128; t++) s += ks2[t*17+ia]*ks2[t*17+ib];
        g_K1[(size_t)bid*DF + f] = s*sc;
    }
}

// ---------------- Phase B: exclusive scan; KV states written as split bf16 ----------------
__global__ __launch_bounds__(256) void scan_kernel() {
    const int bh = blockIdx.x;
    const int part = blockIdx.y;             // 0..17
    const int stride = 18*256;
    size_t baseKV = (size_t)bh*NC*DF*DV;
    for (int idx = part*256 + threadIdx.x; idx < DF*DV; idx += stride) {
        float prev = 0.f;
        size_t p = baseKV + idx;
#pragma unroll
        for (int cc = 0; cc < NC; cc++) {
            float tmp = g_KV[p];
            __nv_bfloat16 hh, ll; split2(prev, hh, ll);
            g_KVbH[p] = hh; g_KVbL[p] = ll;
            prev += tmp;
            p += (size_t)DF*DV;
        }
    }
    if (part == 0) {
        size_t baseK = (size_t)bh*NC*DF;
        for (int idx = threadIdx.x; idx < DF; idx += 256) {
            float prev = 0.f; size_t p = baseK + idx;
#pragma unroll
            for (int cc = 0; cc < NC; cc++) {
                float tmp = g_K1[p]; g_K1[p] = prev; prev += tmp; p += DF;
            }
        }
    }
}

// ---------------- Phase C: fused inter + intra attention via HMMA ----------------
// smem fp32: qT2 [17][128], Ss [128][132], stK [288], dsh [128]
// smem bf16: aH/aL [128][24] ([t][k]); bH/bL [2][16][136] double-buffered ([k][e])
// kT [16][128] fp32 aliases the aH/aL region (dead after S is computed).
#define ATT_AST 24
#define ATT_BST 136
#define ATT_F32 (17*128 + 128*132 + 288 + 128)      // 19488 floats
#define SMEM_C2 (ATT_F32*4 + 2*(128*ATT_AST*2) + 4*(16*ATT_BST*2))   // 107648 B

__global__ __launch_bounds__(256, 2) void attn_kernel() {
    extern __shared__ char smraw[];
    float* qT2 = (float*)smraw;          // [17][128]
    float* Ss  = qT2 + 17*128;           // [128][132]
    float* stK = Ss  + 128*132;          // [288]
    float* dsh = stK + 288;              // [128]
    __nv_bfloat16* aHp = (__nv_bfloat16*)(smraw + ATT_F32*4);   // [128][24]
    __nv_bfloat16* aLp = aHp + 128*ATT_AST;
    __nv_bfloat16* bHp = aLp + 128*ATT_AST;   // [2][16][136]
    __nv_bfloat16* bLp = bHp + 2*16*ATT_BST;
    float* kT = (float*)aHp;             // [16][128], alias; dead after S
    const uint32_t u_aH = smem_to_u32(aHp), u_aL = smem_to_u32(aLp);
    const uint32_t u_bH = smem_to_u32(bHp), u_bL = smem_to_u32(bLp);

    const int bid = blockIdx.x;
    const int bh = bid / NC, c = bid % NC;
    const int b = bh / NH, h = bh % NH;
    const int tid = threadIdx.x, wid = tid >> 5, lane = tid & 31;
    const int wm = wid & 1, wn = wid >> 1;
    const int tx = tid & 15, ty = tid >> 4;
    const size_t rowbase = (size_t)(b*T_ + c*CH);

    for (int idx = tid; idx < 128*16; idx += 256) {
        int t = idx >> 4, i = idx & 15;
        qT2[i*128 + t] = g_qk[(rowbase + t)*NQK + h*DK + i];
        kT [i*128 + t] = g_qk[(rowbase + t)*NQK + 192 + h*DK + i];
    }
    for (int idx = tid; idx < 128; idx += 256) qT2[16*128 + idx] = 1.f;
    for (int f = tid; f < DF; f += 256) stK[f] = g_K1[(size_t)bid*DF + f];
    __syncthreads();

    // ---- S[t][s] = phi(q_t . k_s), causal; phi(x)=1+x/4+x^2/32 (fp32) ----
    {
        float sacc[8][8];
#pragma unroll
        for (int i = 0; i < 8; i++)
#pragma unroll
            for (int j = 0; j < 8; j++) sacc[i][j] = 0.f;
#pragma unroll
        for (int kk = 0; kk < 16; kk++) {
            float a[8], bb[8];
            *(float4*)(a)    = *(const float4*)&qT2[kk*128 + ty*8];
            *(float4*)(a+4)  = *(const float4*)&qT2[kk*128 + ty*8 + 4];
            *(float4*)(bb)   = *(const float4*)&kT [kk*128 + tx*8];
            *(float4*)(bb+4) = *(const float4*)&kT [kk*128 + tx*8 + 4];
#pragma unroll
            for (int i = 0; i < 8; i++)
#pragma unroll
                for (int j = 0; j < 8; j++) sacc[i][j] += a[i]*bb[j];
        }
#pragma unroll
        for (int i = 0; i < 8; i++) {
            int t = ty*8 + i;
#pragma unroll
            for (int j = 0; j < 8; j++) {
                int s = tx*8 + j;
                float d = sacc[i][j];
                Ss[t*132 + s] = (s <= t) ? (1.f + 0.25f*d + 0.03125f*d*d) : 0.f;
            }
        }
    }
    __syncthreads();   // all reads of kT (alias of aHp) complete after this

    // ---- denominators ----
    if (tid < 128) {
        const int t = tid;
        float qv[16];
#pragma unroll
        for (int i = 0; i < 16; i++) qv[i] = qT2[i*128 + t];
        float dacc = stK[0];
#pragma unroll
        for (int i = 0; i < 16; i++) dacc += qv[i]*0.5f*stK[1+i];
#pragma unroll
        for (int i = 0; i < 16; i++) {
            float qi = qv[i]*INV4R2;
#pragma unroll
            for (int j = 0; j < 16; j++)
                dacc += qi*qv[j]*stK[17 + i*16 + j];
        }
        float di = 0.f;
        for (int s = 0; s < 128; s++) di += Ss[t*132 + s];
        dsh[t] = dacc + di + 1e-12f;
    }

    const int arow = (lane & 7) + ((lane >> 3) & 1) * 8;
    const int acol8 = ((lane >> 4) & 1) * 8;

    // B-tile stager: chunk ch -> buffer buf (cp.async; caller commits)
    auto stageB = [&](int chv, int buf) {
        for (int idx = tid; idx < 512; idx += 256) {
            int bufs = idx >> 8;
            int rem = idx & 255;
            int r = rem >> 4, seg = rem & 15;
            uint32_t elem = (uint32_t)(buf*16 + r)*ATT_BST + seg*8;
            uint32_t dst = (bufs == 0 ? u_bH : u_bL) + elem*2;
            if (chv < 18) {
                int f = chv*16 + r;
                if (f < DF) {
                    const __nv_bfloat16* src = (bufs == 0 ? g_KVbH : g_KVbL)
                        + ((size_t)bid*DF + f)*DV + seg*8;
                    CP_ASYNC16(dst, src);
                } else {
                    __nv_bfloat16* base = (bufs == 0 ? bHp : bLp);
                    *(uint4*)&base[elem] = make_uint4(0,0,0,0);
                }
            } else {
                int s0 = (chv - 18)*16;
                const __nv_bfloat16* src = (bufs == 0 ? g_vH : g_vL)
                    + (rowbase + s0 + r)*HID + h*DV + seg*8;
                CP_ASYNC16(dst, src);
            }
        }
    };

    float acc[4][4][4];
#pragma unroll
    for (int i = 0; i < 4; i++)
#pragma unroll
        for (int j = 0; j < 4; j++)
#pragma unroll
            for (int r = 0; r < 4; r++) acc[i][j][r] = 0.f;

    stageB(0, 0); CP_COMMIT();

    // ---- 26 k-chunks: 18 inter (qf @ state) + 8 intra (S @ v) ----
    for (int ch = 0; ch < 26; ch++) {
        const int buf = ch & 1;
        if (ch + 1 < 26) { stageB(ch + 1, buf ^ 1); CP_COMMIT(); }

        // A tile: [t][k=16] computed + split (overlaps with B cp.async in flight)
        if (ch < 18) {
            const int f0 = ch * 16;
            for (int idx = tid; idx < 2048; idx += 256) {
                int t = idx >> 4, kk = idx & 15;
                int f = f0 + kk;
                float val = 0.f;
                if (f < DF) {
                    int ia, ib; float sc; fdecomp(f, ia, ib, sc);
                    val = qT2[ia*128 + t] * qT2[ib*128 + t] * sc;
                }
                __nv_bfloat16 hh, ll; split2(val, hh, ll);
                aHp[t*ATT_AST + kk] = hh; aLp[t*ATT_AST + kk] = ll;
            }
        } else {
            const int s0 = (ch - 18) * 16;
            for (int idx = tid; idx < 2048; idx += 256) {
                int t = idx >> 4, kk = idx & 15;
                float val = Ss[t*132 + s0 + kk];
                __nv_bfloat16 hh, ll; split2(val, hh, ll);
                aHp[t*ATT_AST + kk] = hh; aLp[t*ATT_AST + kk] = ll;
            }
        }
        if (ch + 1 < 26) CP_WAIT1(); else CP_WAIT0();
        __syncthreads();

        uint32_t ah[16], al[16], bhr[8], blr[8];
#pragma unroll
        for (int mb = 0; mb < 4; mb++) {
            const uint32_t off = ((wm*64 + mb*16 + arow) * ATT_AST + acol8) * 2;
            LDSM4(ah[4*mb], ah[4*mb+1], ah[4*mb+2], ah[4*mb+3], u_aH + off);
            LDSM4(al[4*mb], al[4*mb+1], al[4*mb+2], al[4*mb+3], u_aL + off);
        }
#pragma unroll
        for (int nb = 0; nb < 4; nb++) {
            // trans load: rows k = buf*16 + lane%16, col wn*32 + nb*8
            const uint32_t off = ((uint32_t)(buf*16 + (lane & 15)) * ATT_BST + wn*32 + nb*8) * 2;
            LDSM2T(bhr[2*nb], bhr[2*nb+1], u_bH + off);
            LDSM2T(blr[2*nb], blr[2*nb+1], u_bL + off);
        }
#pragma unroll
        for (int mb = 0; mb < 4; mb++)
#pragma unroll
            for (int nb = 0; nb < 4; nb++) {
                MMA16816(acc[mb][nb], &ah[4*mb], &bhr[2*nb]);
                MMA16816(acc[mb][nb], &ah[4*mb], &blr[2*nb]);
                MMA16816(acc[mb][nb], &al[4*mb], &bhr[2*nb]);
            }
        __syncthreads();   // protect aH/aL (and B buf being refilled next iter)
    }

    // ---- epilogue: divide by den, write split bf16 y ----
    const int e0 = wn*32 + 2*(lane & 3);
#pragma unroll
    for (int mb = 0; mb < 4; mb++) {
        int t0 = wm*64 + mb*16 + (lane >> 2);
#pragma unroll
        for (int half = 0; half < 2; half++) {
            int t = t0 + half*8;
            float r = 1.f / dsh[t];
            size_t row = (rowbase + t)*HID + h*DV;
#pragma unroll
            for (int nb = 0; nb < 4; nb++) {
                float y0 = acc[mb][nb][2*half]   * r;
                float y1 = acc[mb][nb][2*half+1] * r;
                __nv_bfloat16 h0, l0, h1, l1;
                split2(y0, h0, l0); split2(y1, h1, l1);
                __nv_bfloat162 hv; hv.x = h0; hv.y = h1;
                __nv_bfloat162 lv; lv.x = l0; lv.y = l1;
                *(__nv_bfloat162*)&g_yH[row + e0 + nb*8] = hv;
                *(__nv_bfloat162*)&g_yL[row + e0 + nb*8] = lv;
            }
        }
    }
}

// ---------------- launch ----------------
extern "C" void kernel_launch(void* const* d_in, const int* in_sizes, int n_in,
                              void* d_out, int out_size) {
    const float* hs = (const float*)d_in[0];
    const float* Wq = (const float*)d_in[1];
    const float* Wk = (const float*)d_in[2];
    const float* Wv = (const float*)d_in[3];
    const float* Wo = (const float*)d_in[4];
    float* out = (float*)d_out;

    float *qk;
    cudaGetSymbolAddress((void**)&qk, g_qk);
    __nv_bfloat16 *hsH, *hsL, *wqkH, *wqkL, *wvH, *wvL, *woH, *woL, *yH, *yL, *vH, *vL;
    cudaGetSymbolAddress((void**)&hsH,  g_hsH);  cudaGetSymbolAddress((void**)&hsL,  g_hsL);
    cudaGetSymbolAddress((void**)&wqkH, g_wqkH); cudaGetSymbolAddress((void**)&wqkL, g_wqkL);
    cudaGetSymbolAddress((void**)&wvH,  g_wvH);  cudaGetSymbolAddress((void**)&wvL,  g_wvL);
    cudaGetSymbolAddress((void**)&woH,  g_woH);  cudaGetSymbolAddress((void**)&woL,  g_woL);
    cudaGetSymbolAddress((void**)&yH,   g_yH);   cudaGetSymbolAddress((void**)&yL,   g_yL);
    cudaGetSymbolAddress((void**)&vH,   g_vH);   cudaGetSymbolAddress((void**)&vL,   g_vL);

    cudaFuncSetAttribute(chunk_kv_kernel, cudaFuncAttributeMaxDynamicSharedMemorySize, SMEM_A2);
    cudaFuncSetAttribute(attn_kernel,     cudaFuncAttributeMaxDynamicSharedMemorySize, SMEM_C2);
    cudaFuncSetAttribute(gemm_hmma<0>,    cudaFuncAttributeMaxDynamicSharedMemorySize, SMEM_G);
    cudaFuncSetAttribute(gemm_hmma<1>,    cudaFuncAttributeMaxDynamicSharedMemorySize, SMEM_G);

    dim3 thr(256);
    conv_all<<<592, thr>>>(hs, Wq, Wk, Wv, Wo);

    // projections
    gemm_hmma<0><<<dim3(NQK/128, MROWS/128), thr, SMEM_G>>>(hsH, hsL, wqkH, wqkL, qk, nullptr, nullptr, NQK);
    gemm_hmma<1><<<dim3(HID/128, MROWS/128), thr, SMEM_G>>>(hsH, hsL, wvH, wvL, nullptr, vH, vL, HID);

    chunk_kv_kernel<<<BH*NC, thr, SMEM_A2>>>();
    scan_kernel<<<dim3(BH, 18), thr>>>();
    attn_kernel<<<BH*NC, thr, SMEM_C2>>>();

    gemm_hmma<0><<<dim3(HID/128, MROWS/128), thr, SMEM_G>>>(yH, yL, woH, woL, out, nullptr, nullptr, HID);
}